// round 4
// baseline (speedup 1.0000x reference)
#include <cuda_runtime.h>
#include <math.h>

// ---------------- model constants ----------------
constexpr int L_ = 12, H_ = 12, D_ = 768, HD_ = 64, MFF = 3072, B_ = 32, NC_ = 1000;
constexpr int NP = 576;            // patches per image (24x24)
constexpr int S_ = NP + 1;         // 577 tokens
constexpr int BS_ = B_ * S_;       // 18464 rows
constexpr float SCALE_ = 0.125f;   // 1/sqrt(64)

// ---------------- scratch (single device global, no allocation) ----------------
constexpr size_t BSD      = (size_t)BS_ * D_;            // 14,180,352
constexpr size_t O_X      = 0;
constexpr size_t O_H      = O_X + BSD;
constexpr size_t O_H2     = O_H + BSD;
constexpr size_t O_O      = O_H2 + BSD;
constexpr size_t O_QKV    = O_O + BSD;
constexpr size_t SZ_QKV   = BSD * 3;
constexpr size_t O_ATTN   = O_QKV + SZ_QKV;
constexpr size_t SZ_ATTN  = (size_t)B_ * H_ * S_ * S_;   // 127,844,736
constexpr size_t O_M1     = O_ATTN + SZ_ATTN;
constexpr size_t SZ_M1    = (size_t)BS_ * MFF;           // 56,721,408
constexpr size_t O_WPACK  = O_M1 + SZ_M1;
constexpr size_t SZ_WPACK = (size_t)L_ * D_ * 3 * D_;
constexpr size_t O_BPACK  = O_WPACK + SZ_WPACK;
constexpr size_t O_WPATCH = O_BPACK + (size_t)L_ * 3 * D_;
constexpr size_t O_CLS    = O_WPATCH + (size_t)D_ * D_;
constexpr size_t O_LOGITS = O_CLS + (size_t)B_ * D_;
constexpr size_t TOTALF   = O_LOGITS + (size_t)B_ * NC_;

__device__ __align__(16) float g_buf[TOTALF];

static inline int cdiv(int a, int b) { return (a + b - 1) / b; }

// ---------------- weight repack ----------------
// wqkv [L,H,D,192] -> wpack [L, D, 2304] with col layout: part(q/k/v)*768 + h*64 + e
__global__ void pack_wqkv_kernel(const float* __restrict__ wqkv, float* __restrict__ wp) {
    long long idx = (long long)blockIdx.x * blockDim.x + threadIdx.x;
    long long total = (long long)L_ * H_ * D_ * 192;
    if (idx >= total) return;
    int ef = (int)(idx % 192);
    long long r = idx / 192;
    int d = (int)(r % D_); r /= D_;
    int h = (int)(r % H_);
    int l = (int)(r / H_);
    int part = ef / 64, e = ef % 64;
    wp[((size_t)l * D_ + d) * 2304 + part * 768 + h * 64 + e] = wqkv[idx];
}

__global__ void pack_bqkv_kernel(const float* __restrict__ bqkv, float* __restrict__ bp) {
    int idx = blockIdx.x * blockDim.x + threadIdx.x;
    int total = L_ * H_ * 192;
    if (idx >= total) return;
    int ef = idx % 192;
    int r = idx / 192;
    int h = r % H_;
    int l = r / H_;
    int part = ef / 64, e = ef % 64;
    bp[(size_t)l * 2304 + part * 768 + h * 64 + e] = bqkv[idx];
}

// conv_w [768, 768(c,ky,kx)] -> transposed [768(k), 768(d)]
__global__ void transpose_w_kernel(const float* __restrict__ w, float* __restrict__ wt) {
    int idx = blockIdx.x * blockDim.x + threadIdx.x;
    if (idx >= D_ * D_) return;
    int d = idx / D_, k = idx % D_;
    wt[(size_t)k * D_ + d] = w[idx];
}

// ---------------- im2col for 16x16/stride16 conv ----------------
__global__ void im2col_kernel(const float* __restrict__ x, float* __restrict__ A) {
    long long idx = (long long)blockIdx.x * blockDim.x + threadIdx.x;
    long long total = (long long)B_ * NP * D_;
    if (idx >= total) return;
    int k = (int)(idx % D_);        // (c,ky,kx)
    long long bp = idx / D_;
    int p = (int)(bp % NP);
    int b = (int)(bp / NP);
    int c = k >> 8;
    int ky = (k >> 4) & 15;
    int kx = k & 15;
    int py = p / 24, px = p % 24;
    A[idx] = x[(((size_t)b * 3 + c) * 384 + py * 16 + ky) * 384 + px * 16 + kx];
}

// ---------------- token assembly (faithful channel-major reshape + cls + pos) ----------------
__global__ void assemble_tokens_kernel(const float* __restrict__ cpatch, const float* __restrict__ cls_t,
                                       const float* __restrict__ pos, float* __restrict__ x) {
    long long idx = (long long)blockIdx.x * blockDim.x + threadIdx.x;
    long long total = (long long)B_ * S_ * D_;
    if (idx >= total) return;
    int j = (int)(idx % D_);
    long long bi = idx / D_;
    int i = (int)(bi % S_);
    int b = (int)(bi / S_);
    float v;
    if (i == 0) {
        v = cls_t[j];
    } else {
        int flat = (i - 1) * D_ + j;          // = d*576 + p
        int d = flat / NP;
        int p = flat % NP;
        v = cpatch[((size_t)b * NP + p) * D_ + d];
    }
    x[idx] = v + pos[(size_t)i * D_ + j];
}

// ---------------- generic tiled SGEMM: C = act(A[M,K]@B[K,N] + bias + res) ----------------
// Requirements honored by all call sites: K % 16 == 0, N % 4 == 0,
// A/B/C/res base pointers 16B-aligned with rows 16B-aligned (K,N mult of 4).
constexpr int BM = 128, BN = 128, BK = 16, TM = 8, TN = 8;

__global__ __launch_bounds__(256) void gemm_kernel(
    const float* __restrict__ A, const float* __restrict__ Bm,
    const float* __restrict__ bias, const float* __restrict__ res,
    float* __restrict__ C, int Mr, int N, int K, int act) {
    __shared__ float As[BK][BM + 4];   // transposed A tile (+4 pad keeps 16B store alignment)
    __shared__ float Bs[BK][BN];
    int t = threadIdx.x;
    int bm = blockIdx.y * BM, bn = blockIdx.x * BN;
    int tm = (t / 16) * TM, tn = (t % 16) * TN;
    float acc[TM][TN] = {};

    // Per-thread load slots: 2 float4 for A, 2 float4 for B per K-tile.
    // A mapping: vec v -> row m = v>>2 (0..127), col4 = (v&3)*4 within the 16-wide K slab.
    // B mapping: vec v -> row kk = v>>5 (0..15), col4 = (v&31)*4 within the 128-wide N slab.
    const int am0 = t >> 2,          ac0 = (t & 3) * 4;
    const int am1 = (t + 256) >> 2,  ac1 = ((t + 256) & 3) * 4;
    const int bk0 = t >> 5,          bc0 = (t & 31) * 4;
    const int bk1 = (t + 256) >> 5,  bc1 = ((t + 256) & 31) * 4;

    float4 ra0, ra1, rb0, rb1;

    auto load_tile = [&](int k0) {
        // A loads (row guard on M)
        ra0 = make_float4(0.f, 0.f, 0.f, 0.f);
        ra1 = make_float4(0.f, 0.f, 0.f, 0.f);
        int gm0 = bm + am0, gm1 = bm + am1;
        if (gm0 < Mr) ra0 = *(const float4*)(A + (size_t)gm0 * K + k0 + ac0);
        if (gm1 < Mr) ra1 = *(const float4*)(A + (size_t)gm1 * K + k0 + ac1);
        // B loads (col guard on N; K exact by contract)
        rb0 = make_float4(0.f, 0.f, 0.f, 0.f);
        rb1 = make_float4(0.f, 0.f, 0.f, 0.f);
        int gn0 = bn + bc0, gn1 = bn + bc1;
        const float* p0 = Bm + (size_t)(k0 + bk0) * N;
        const float* p1 = Bm + (size_t)(k0 + bk1) * N;
        if (gn0 + 3 < N) rb0 = *(const float4*)(p0 + gn0);
        else if (gn0 < N) {
            rb0.x = p0[gn0];
            if (gn0 + 1 < N) rb0.y = p0[gn0 + 1];
            if (gn0 + 2 < N) rb0.z = p0[gn0 + 2];
        }
        if (gn1 + 3 < N) rb1 = *(const float4*)(p1 + gn1);
        else if (gn1 < N) {
            rb1.x = p1[gn1];
            if (gn1 + 1 < N) rb1.y = p1[gn1 + 1];
            if (gn1 + 2 < N) rb1.z = p1[gn1 + 2];
        }
    };

    load_tile(0);
    for (int k0 = 0; k0 < K; k0 += BK) {
        // stage current tile to smem
        As[ac0 + 0][am0] = ra0.x; As[ac0 + 1][am0] = ra0.y;
        As[ac0 + 2][am0] = ra0.z; As[ac0 + 3][am0] = ra0.w;
        As[ac1 + 0][am1] = ra1.x; As[ac1 + 1][am1] = ra1.y;
        As[ac1 + 2][am1] = ra1.z; As[ac1 + 3][am1] = ra1.w;
        *(float4*)(&Bs[bk0][bc0]) = rb0;
        *(float4*)(&Bs[bk1][bc1]) = rb1;
        __syncthreads();
        // prefetch next tile (overlaps with compute below)
        if (k0 + BK < K) load_tile(k0 + BK);
        #pragma unroll
        for (int kk = 0; kk < BK; kk++) {
            float a[TM], b[TN];
            #pragma unroll
            for (int i = 0; i < TM; i++) a[i] = As[kk][tm + i];
            #pragma unroll
            for (int j = 0; j < TN; j++) b[j] = Bs[kk][tn + j];
            #pragma unroll
            for (int i = 0; i < TM; i++)
                #pragma unroll
                for (int j = 0; j < TN; j++)
                    acc[i][j] += a[i] * b[j];
        }
        __syncthreads();
    }
    #pragma unroll
    for (int i = 0; i < TM; i++) {
        int gm = bm + tm + i;
        if (gm >= Mr) continue;
        #pragma unroll
        for (int j = 0; j < TN; j++) {
            int gn = bn + tn + j;
            if (gn >= N) continue;
            float v = acc[i][j];
            if (bias) v += bias[gn];
            if (res) v += res[(size_t)gm * N + gn];
            if (act == 1) v = 0.5f * v * (1.f + erff(v * 0.70710678118654752f));
            C[(size_t)gm * N + gn] = v;
        }
    }
}

// ---------------- LayerNorm (D=768 fixed, 256 thr/row, strided rows) ----------------
__global__ __launch_bounds__(256) void ln_kernel(const float* __restrict__ in, float* __restrict__ out,
                                                 const float* __restrict__ g, const float* __restrict__ bb,
                                                 long long stride_in, long long stride_out) {
    long long r = blockIdx.x;
    const float* p = in + r * stride_in;
    float* po = out + r * stride_out;
    int t = threadIdx.x;
    float v0 = p[t], v1 = p[t + 256], v2 = p[t + 512];
    __shared__ float red[256];
    red[t] = v0 + v1 + v2;
    __syncthreads();
    for (int s = 128; s > 0; s >>= 1) { if (t < s) red[t] += red[t + s]; __syncthreads(); }
    float mu = red[0] * (1.f / 768.f);
    __syncthreads();
    float d0 = v0 - mu, d1 = v1 - mu, d2 = v2 - mu;
    red[t] = d0 * d0 + d1 * d1 + d2 * d2;
    __syncthreads();
    for (int s = 128; s > 0; s >>= 1) { if (t < s) red[t] += red[t + s]; __syncthreads(); }
    float rstd = rsqrtf(red[0] * (1.f / 768.f) + 1e-5f);
    __syncthreads();
    po[t]       = d0 * rstd * g[t]       + bb[t];
    po[t + 256] = d1 * rstd * g[t + 256] + bb[t + 256];
    po[t + 512] = d2 * rstd * g[t + 512] + bb[t + 512];
}

// ---------------- attention scores: S[b,h,q,k] = scale * q.k ----------------
__global__ __launch_bounds__(256) void attn_scores_kernel(const float* __restrict__ qkv, float* __restrict__ attn) {
    int bh = blockIdx.z;
    int b = bh / H_, h = bh % H_;
    int q0 = blockIdx.y * 64, k0 = blockIdx.x * 64;
    __shared__ float Qs[64][65], Ks[64][65];
    int t = threadIdx.x;
    #pragma unroll
    for (int i = 0; i < 16; i++) {
        int e = t + i * 256;
        int r = e >> 6, c = e & 63;
        int gq = q0 + r;
        Qs[r][c] = (gq < S_) ? qkv[(size_t)(b * S_ + gq) * 2304 + h * 64 + c] : 0.f;
        int gk = k0 + r;
        Ks[r][c] = (gk < S_) ? qkv[(size_t)(b * S_ + gk) * 2304 + 768 + h * 64 + c] : 0.f;
    }
    __syncthreads();
    int tm = (t / 16) * 4, tn = (t % 16) * 4;
    float acc[4][4] = {};
    #pragma unroll
    for (int e = 0; e < 64; e++) {
        float a[4], bv[4];
        #pragma unroll
        for (int i = 0; i < 4; i++) a[i] = Qs[tm + i][e];
        #pragma unroll
        for (int j = 0; j < 4; j++) bv[j] = Ks[tn + j][e];
        #pragma unroll
        for (int i = 0; i < 4; i++)
            #pragma unroll
            for (int j = 0; j < 4; j++)
                acc[i][j] += a[i] * bv[j];
    }
    #pragma unroll
    for (int i = 0; i < 4; i++) {
        int gq = q0 + tm + i;
        if (gq >= S_) continue;
        #pragma unroll
        for (int j = 0; j < 4; j++) {
            int gk = k0 + tn + j;
            if (gk >= S_) continue;
            attn[((size_t)bh * S_ + gq) * S_ + gk] = acc[i][j] * SCALE_;
        }
    }
}

// ---------------- row softmax ----------------
__global__ __launch_bounds__(256) void softmax_kernel(const float* __restrict__ in, float* __restrict__ out, int len) {
    long long row = blockIdx.x;
    const float* p = in + row * (long long)len;
    float* po = out + row * (long long)len;
    int t = threadIdx.x;
    __shared__ float red[256];
    float mx = -1e30f;
    for (int i = t; i < len; i += 256) mx = fmaxf(mx, p[i]);
    red[t] = mx; __syncthreads();
    for (int s = 128; s > 0; s >>= 1) { if (t < s) red[t] = fmaxf(red[t], red[t + s]); __syncthreads(); }
    mx = red[0]; __syncthreads();
    float sum = 0.f;
    for (int i = t; i < len; i += 256) { float e = expf(p[i] - mx); po[i] = e; sum += e; }
    red[t] = sum; __syncthreads();
    for (int s = 128; s > 0; s >>= 1) { if (t < s) red[t] += red[t + s]; __syncthreads(); }
    float inv = 1.f / red[0];
    __syncthreads();
    for (int i = t; i < len; i += 256) po[i] *= inv;
}

// ---------------- O = P @ V (batched over b,h) ----------------
__global__ __launch_bounds__(256) void attn_av_kernel(const float* __restrict__ attn, const float* __restrict__ qkv,
                                                      float* __restrict__ o) {
    int bh = blockIdx.y;
    int b = bh / H_, h = bh % H_;
    int m0 = blockIdx.x * 64;
    __shared__ float Ps[64][33], Vs[32][64];
    int t = threadIdx.x;
    int tm = (t / 16) * 4, tn = (t % 16) * 4;
    float acc[4][4] = {};
    for (int k0 = 0; k0 < S_; k0 += 32) {
        #pragma unroll
        for (int i = 0; i < 8; i++) {
            int e = t + i * 256;
            int r = e >> 5, c = e & 31;
            int gm = m0 + r, gk = k0 + c;
            Ps[r][c] = (gm < S_ && gk < S_) ? attn[((size_t)bh * S_ + gm) * S_ + gk] : 0.f;
        }
        #pragma unroll
        for (int i = 0; i < 8; i++) {
            int e = t + i * 256;
            int r = e >> 6, c = e & 63;
            int gk = k0 + r;
            Vs[r][c] = (gk < S_) ? qkv[(size_t)(b * S_ + gk) * 2304 + 1536 + h * 64 + c] : 0.f;
        }
        __syncthreads();
        #pragma unroll
        for (int kk = 0; kk < 32; kk++) {
            float a[4], bv[4];
            #pragma unroll
            for (int i = 0; i < 4; i++) a[i] = Ps[tm + i][kk];
            #pragma unroll
            for (int j = 0; j < 4; j++) bv[j] = Vs[kk][tn + j];
            #pragma unroll
            for (int i = 0; i < 4; i++)
                #pragma unroll
                for (int j = 0; j < 4; j++)
                    acc[i][j] += a[i] * bv[j];
        }
        __syncthreads();
    }
    #pragma unroll
    for (int i = 0; i < 4; i++) {
        int gm = m0 + tm + i;
        if (gm >= S_) continue;
        #pragma unroll
        for (int j = 0; j < 4; j++) {
            o[(size_t)(b * S_ + gm) * D_ + h * 64 + tn + j] = acc[i][j];
        }
    }
}

// ---------------- host orchestration ----------------
extern "C" void kernel_launch(void* const* d_in, const int* in_sizes, int n_in,
                              void* d_out, int out_size) {
    const float* x      = (const float*)d_in[0];
    const float* conv_w = (const float*)d_in[1];
    const float* conv_b = (const float*)d_in[2];
    const float* cls_t  = (const float*)d_in[3];
    const float* pos    = (const float*)d_in[4];
    const float* ln1_g  = (const float*)d_in[5];
    const float* ln1_b  = (const float*)d_in[6];
    const float* wqkv   = (const float*)d_in[7];
    const float* bqkv   = (const float*)d_in[8];
    const float* wmsa   = (const float*)d_in[9];
    const float* bmsa   = (const float*)d_in[10];
    const float* ln2_g  = (const float*)d_in[11];
    const float* ln2_b  = (const float*)d_in[12];
    const float* lnm_g  = (const float*)d_in[13];
    const float* lnm_b  = (const float*)d_in[14];
    const float* w1     = (const float*)d_in[15];
    const float* b1     = (const float*)d_in[16];
    const float* w2     = (const float*)d_in[17];
    const float* b2     = (const float*)d_in[18];
    const float* lnf_g  = (const float*)d_in[19];
    const float* lnf_b  = (const float*)d_in[20];
    const float* whead  = (const float*)d_in[21];
    const float* bhead  = (const float*)d_in[22];
    float* out = (float*)d_out;

    float* buf = nullptr;
    cudaGetSymbolAddress((void**)&buf, g_buf);
    float* px      = buf + O_X;
    float* ph      = buf + O_H;
    float* ph2     = buf + O_H2;
    float* po      = buf + O_O;
    float* pqkv    = buf + O_QKV;
    float* pattn   = buf + O_ATTN;
    float* pm1     = buf + O_M1;
    float* pwpack  = buf + O_WPACK;
    float* pbpack  = buf + O_BPACK;
    float* pwpatch = buf + O_WPATCH;
    float* pcls    = buf + O_CLS;
    float* plogits = buf + O_LOGITS;

    // --- weight repack + patch embedding ---
    pack_wqkv_kernel<<<cdiv(L_ * H_ * D_ * 192, 256), 256>>>(wqkv, pwpack);
    pack_bqkv_kernel<<<cdiv(L_ * H_ * 192, 256), 256>>>(bqkv, pbpack);
    transpose_w_kernel<<<cdiv(D_ * D_, 256), 256>>>(conv_w, pwpatch);
    im2col_kernel<<<cdiv(B_ * NP * D_, 256), 256>>>(x, ph);
    gemm_kernel<<<dim3(cdiv(D_, BN), cdiv(B_ * NP, BM)), 256>>>(
        ph, pwpatch, conv_b, nullptr, pqkv, B_ * NP, D_, D_, 0);
    assemble_tokens_kernel<<<cdiv(B_ * S_ * D_, 256), 256>>>(pqkv, cls_t, pos, px);

    // --- encoder blocks ---
    for (int l = 0; l < L_; l++) {
        ln_kernel<<<BS_, 256>>>(px, ph, ln1_g + (size_t)l * D_, ln1_b + (size_t)l * D_, D_, D_);
        gemm_kernel<<<dim3(cdiv(3 * D_, BN), cdiv(BS_, BM)), 256>>>(
            ph, pwpack + (size_t)l * D_ * 3 * D_, pbpack + (size_t)l * 3 * D_, nullptr,
            pqkv, BS_, 3 * D_, D_, 0);
        attn_scores_kernel<<<dim3(cdiv(S_, 64), cdiv(S_, 64), B_ * H_), 256>>>(pqkv, pattn);
        softmax_kernel<<<B_ * H_ * S_, 256>>>(pattn, pattn, S_);
        attn_av_kernel<<<dim3(cdiv(S_, 64), B_ * H_), 256>>>(pattn, pqkv, po);
        // x1 = h + (o @ wmsa + bmsa), written over x
        gemm_kernel<<<dim3(cdiv(D_, BN), cdiv(BS_, BM)), 256>>>(
            po, wmsa + (size_t)l * D_ * D_, bmsa + (size_t)l * D_, ph, px, BS_, D_, D_, 0);
        ln_kernel<<<BS_, 256>>>(px, ph2, ln2_g + (size_t)l * D_, ln2_b + (size_t)l * D_, D_, D_);
        ln_kernel<<<BS_, 256>>>(ph2, ph2, lnm_g + (size_t)l * D_, lnm_b + (size_t)l * D_, D_, D_);
        gemm_kernel<<<dim3(cdiv(MFF, BN), cdiv(BS_, BM)), 256>>>(
            ph2, w1 + (size_t)l * D_ * MFF, b1 + (size_t)l * MFF, nullptr, pm1, BS_, MFF, D_, 1);
        gemm_kernel<<<dim3(cdiv(D_, BN), cdiv(BS_, BM)), 256>>>(
            pm1, w2 + (size_t)l * MFF * D_, b2 + (size_t)l * D_, px, px, BS_, D_, MFF, 0);
    }

    // --- head ---
    ln_kernel<<<B_, 256>>>(px, pcls, lnf_g, lnf_b, (long long)S_ * D_, D_);
    gemm_kernel<<<dim3(cdiv(NC_, BN), cdiv(B_, BM)), 256>>>(
        pcls, whead, bhead, nullptr, plogits, B_, NC_, D_, 0);
    softmax_kernel<<<B_, 256>>>(plogits, out, NC_);
}

// round 13
// speedup vs baseline: 1.8442x; 1.8442x over previous
#include <cuda_runtime.h>
#include <cuda_bf16.h>
#include <math.h>
#include <stdint.h>

constexpr int L_ = 12, H_ = 12, D_ = 768, MFF = 3072, B_ = 32, NC_ = 1000;
constexpr int NP = 576, S_ = NP + 1, BS_ = B_ * S_;
constexpr float SCALE_ = 0.125f;

constexpr size_t BSD      = (size_t)BS_ * D_;
constexpr size_t O_X      = 0;
constexpr size_t O_H      = O_X + BSD;
constexpr size_t O_H2     = O_H + BSD;
constexpr size_t O_O      = O_H2 + BSD;
constexpr size_t O_QKV    = O_O + BSD;
constexpr size_t O_ATTN   = O_QKV + BSD * 3;
constexpr size_t O_M1     = O_ATTN + (size_t)B_ * H_ * S_ * S_;
constexpr size_t SZ_QKVW  = (size_t)L_ * 2304 * 768 / 2;
constexpr size_t SZ_PW    = (size_t)768 * 768 / 2;
constexpr size_t SZ_MSAW  = (size_t)L_ * 768 * 768 / 2;
constexpr size_t SZ_W1    = (size_t)L_ * 3072 * 768 / 2;
constexpr size_t O_QKVH   = O_M1 + (size_t)BS_ * MFF;
constexpr size_t O_QKVL   = O_QKVH + SZ_QKVW;
constexpr size_t O_PWH    = O_QKVL + SZ_QKVW;
constexpr size_t O_PWL    = O_PWH + SZ_PW;
constexpr size_t O_MSAH   = O_PWL + SZ_PW;
constexpr size_t O_MSAL   = O_MSAH + SZ_MSAW;
constexpr size_t O_W1H    = O_MSAL + SZ_MSAW;
constexpr size_t O_W1L    = O_W1H + SZ_W1;
constexpr size_t O_W2H    = O_W1L + SZ_W1;
constexpr size_t O_W2L    = O_W2H + SZ_W1;
constexpr size_t O_BPACK  = O_W2L + SZ_W1;
constexpr size_t O_CLS    = O_BPACK + (size_t)L_ * 2304;
constexpr size_t O_LOGITS = O_CLS + (size_t)B_ * D_;
constexpr size_t TOTALF   = O_LOGITS + (size_t)B_ * NC_;

__device__ __align__(16) float g_buf[TOTALF];

static inline int cdiv(int a, int b) { return (a + b - 1) / b; }

typedef __nv_bfloat16 bf16;

__device__ __forceinline__ void split2(float a, float b, uint32_t& h, uint32_t& l) {
    __nv_bfloat16 ha = __float2bfloat16_rn(a), hb = __float2bfloat16_rn(b);
    __nv_bfloat162 vh = __halves2bfloat162(ha, hb);
    __nv_bfloat162 vl = __halves2bfloat162(__float2bfloat16_rn(a - __bfloat162float(ha)),
                                           __float2bfloat16_rn(b - __bfloat162float(hb)));
    h = *(uint32_t*)&vh; l = *(uint32_t*)&vl;
}

// m16n8k16 bf16 mma (sm_80+ PTX, no arch-specific features)
__device__ __forceinline__ void mma16816(float* d, const uint32_t* a, uint32_t b0, uint32_t b1) {
    asm volatile(
        "mma.sync.aligned.m16n8k16.row.col.f32.bf16.bf16.f32 "
        "{%0,%1,%2,%3}, {%4,%5,%6,%7}, {%8,%9}, {%0,%1,%2,%3};"
        : "+f"(d[0]), "+f"(d[1]), "+f"(d[2]), "+f"(d[3])
        : "r"(a[0]), "r"(a[1]), "r"(a[2]), "r"(a[3]), "r"(b0), "r"(b1));
}

// ====== HMMA GEMM: C = act(A[M,K]fp32 @ B[K,N] + bias + res), B pre-split bf16 [N,K] ======
// tile 128x128, 8 warps (2x4), each warp 64x32 via 4x4 m16n8k16. 3-term bf16 split.
constexpr int AST = 72;                      // padded smem stride (bf16 units) -> conflict-free frags
constexpr int TILE_E = 128 * AST;            // bf16 per array
constexpr int MM_SMEM = 4 * TILE_E * 2;      // 73728 bytes (AH AL BH BL)

__global__ void __launch_bounds__(256, 2) gemm_mma_kernel(
    const float* __restrict__ A, const bf16* __restrict__ Bh, const bf16* __restrict__ Bl,
    const float* __restrict__ bias, const float* __restrict__ res,
    float* __restrict__ C, int Mr, int N, int K, int act) {
    extern __shared__ bf16 sm[];
    bf16* AH = sm;
    bf16* AL = sm + TILE_E;
    bf16* BH = sm + 2 * TILE_E;
    bf16* BL = sm + 3 * TILE_E;
    const int t = threadIdx.x, lane = t & 31, warp = t >> 5;
    const int bm = blockIdx.y * 128, bn = blockIdx.x * 128;
    const int wm = (warp >> 2) * 64, wn = (warp & 3) * 32;
    const int lq = lane >> 2, kp = lane & 3;
    float acc[4][4][4] = {};

    for (int c = 0; c < K / 64; c++) {
        const int kc0 = c * 64;
        // stage A chunk [128m x 64k] fp32 -> split hi/lo (1024 slots of 8 bf16)
        #pragma unroll
        for (int j = 0; j < 4; j++) {
            int v = t + j * 256;
            int m = v >> 3, k8 = (v & 7) * 8;
            float4 f0 = make_float4(0,0,0,0), f1 = make_float4(0,0,0,0);
            int gm = bm + m;
            if (gm < Mr) {
                const float* p = A + (size_t)gm * K + kc0 + k8;
                f0 = *(const float4*)p; f1 = *(const float4*)(p + 4);
            }
            uint4 hi, lo;
            split2(f0.x, f0.y, hi.x, lo.x); split2(f0.z, f0.w, hi.y, lo.y);
            split2(f1.x, f1.y, hi.z, lo.z); split2(f1.z, f1.w, hi.w, lo.w);
            *(uint4*)&AH[m * AST + k8] = hi;
            *(uint4*)&AL[m * AST + k8] = lo;
        }
        // stage B chunk [128n x 64k] bf16 hi/lo direct copy
        #pragma unroll
        for (int j = 0; j < 4; j++) {
            int v = t + j * 256;
            int n = v >> 3, k8 = (v & 7) * 8;
            size_t go = (size_t)(bn + n) * K + kc0 + k8;
            *(uint4*)&BH[n * AST + k8] = *(const uint4*)(Bh + go);
            *(uint4*)&BL[n * AST + k8] = *(const uint4*)(Bl + go);
        }
        __syncthreads();
        #pragma unroll
        for (int ks = 0; ks < 4; ks++) {
            const int k16 = ks * 16;
            const int cA = k16 + kp * 2;
            uint32_t ah[4][4], al[4][4];
            #pragma unroll
            for (int mt = 0; mt < 4; mt++) {
                int r0 = wm + mt * 16 + lq;
                ah[mt][0] = *(uint32_t*)&AH[r0 * AST + cA];
                ah[mt][1] = *(uint32_t*)&AH[(r0 + 8) * AST + cA];
                ah[mt][2] = *(uint32_t*)&AH[r0 * AST + cA + 8];
                ah[mt][3] = *(uint32_t*)&AH[(r0 + 8) * AST + cA + 8];
                al[mt][0] = *(uint32_t*)&AL[r0 * AST + cA];
                al[mt][1] = *(uint32_t*)&AL[(r0 + 8) * AST + cA];
                al[mt][2] = *(uint32_t*)&AL[r0 * AST + cA + 8];
                al[mt][3] = *(uint32_t*)&AL[(r0 + 8) * AST + cA + 8];
            }
            #pragma unroll
            for (int nt = 0; nt < 4; nt++) {
                int n0 = wn + nt * 8 + lq;
                uint32_t bh0 = *(uint32_t*)&BH[n0 * AST + cA];
                uint32_t bh1 = *(uint32_t*)&BH[n0 * AST + cA + 8];
                uint32_t bl0 = *(uint32_t*)&BL[n0 * AST + cA];
                uint32_t bl1 = *(uint32_t*)&BL[n0 * AST + cA + 8];
                #pragma unroll
                for (int mt = 0; mt < 4; mt++) {
                    mma16816(acc[mt][nt], ah[mt], bh0, bh1);
                    mma16816(acc[mt][nt], al[mt], bh0, bh1);
                    mma16816(acc[mt][nt], ah[mt], bl0, bl1);
                }
            }
        }
        __syncthreads();
    }
    // epilogue: direct register -> gmem (frag layout: rows lq/+8, cols 2*kp)
    #pragma unroll
    for (int mt = 0; mt < 4; mt++) {
        #pragma unroll
        for (int half = 0; half < 2; half++) {
            int gm = bm + wm + mt * 16 + lq + half * 8;
            if (gm >= Mr) continue;
            #pragma unroll
            for (int nt = 0; nt < 4; nt++) {
                int gc = bn + wn + nt * 8 + kp * 2;
                float v0 = acc[mt][nt][half * 2 + 0];
                float v1 = acc[mt][nt][half * 2 + 1];
                if (bias) { v0 += bias[gc]; v1 += bias[gc + 1]; }
                if (res) {
                    float2 rv = *(const float2*)(res + (size_t)gm * N + gc);
                    v0 += rv.x; v1 += rv.y;
                }
                if (act == 1) {
                    v0 = 0.5f * v0 * (1.f + erff(v0 * 0.70710678f));
                    v1 = 0.5f * v1 * (1.f + erff(v1 * 0.70710678f));
                }
                *(float2*)(C + (size_t)gm * N + gc) = make_float2(v0, v1);
            }
        }
    }
}

// ====== weight pre-split kernels ======
__global__ void split_transpose_kernel(const float* __restrict__ in, bf16* __restrict__ hi,
                                       bf16* __restrict__ lo, int K, int N) {
    __shared__ float tile[32][33];
    size_t bo = (size_t)blockIdx.z * K * N;
    int k0 = blockIdx.y * 32, n0 = blockIdx.x * 32;
    int tx = threadIdx.x & 31, ty = threadIdx.x >> 5;
    for (int i = ty; i < 32; i += 8)
        tile[i][tx] = in[bo + (size_t)(k0 + i) * N + n0 + tx];
    __syncthreads();
    for (int i = ty; i < 32; i += 8) {
        float v = tile[tx][i];
        bf16 h = __float2bfloat16_rn(v);
        size_t o = bo + (size_t)(n0 + i) * K + k0 + tx;
        hi[o] = h;
        lo[o] = __float2bfloat16_rn(v - __bfloat162float(h));
    }
}
__global__ void split_kernel(const float* __restrict__ in, bf16* __restrict__ hi,
                             bf16* __restrict__ lo, long long n) {
    long long i = (long long)blockIdx.x * blockDim.x + threadIdx.x;
    if (i >= n) return;
    float v = in[i];
    bf16 h = __float2bfloat16_rn(v);
    hi[i] = h;
    lo[i] = __float2bfloat16_rn(v - __bfloat162float(h));
}
__global__ void pack_wqkv_split_kernel(const float* __restrict__ w, bf16* __restrict__ hi,
                                       bf16* __restrict__ lo) {
    long long idx = (long long)blockIdx.x * blockDim.x + threadIdx.x;
    if (idx >= (long long)L_ * 2304 * 768) return;
    int d = (int)(idx % 768);
    long long r = idx / 768;
    int n = (int)(r % 2304), l = (int)(r / 2304);
    int part = n / 768, h = (n % 768) / 64, e = n % 64;
    float v = w[(((size_t)l * H_ + h) * D_ + d) * 192 + part * 64 + e];
    bf16 hh = __float2bfloat16_rn(v);
    hi[idx] = hh;
    lo[idx] = __float2bfloat16_rn(v - __bfloat162float(hh));
}
__global__ void pack_bqkv_kernel(const float* __restrict__ b, float* __restrict__ bp) {
    int idx = blockIdx.x * blockDim.x + threadIdx.x;
    if (idx >= L_ * H_ * 192) return;
    int ef = idx % 192, r = idx / 192, h = r % H_, l = r / H_;
    bp[(size_t)l * 2304 + (ef / 64) * 768 + h * 64 + (ef % 64)] = b[idx];
}

// ====== im2col / token assembly ======
__global__ void im2col_kernel(const float* __restrict__ x, float* __restrict__ A) {
    long long idx = (long long)blockIdx.x * blockDim.x + threadIdx.x;
    if (idx >= (long long)B_ * NP * D_) return;
    int k = (int)(idx % D_); long long bp = idx / D_;
    int p = (int)(bp % NP), b = (int)(bp / NP);
    int c = k >> 8, ky = (k >> 4) & 15, kx = k & 15;
    A[idx] = x[(((size_t)b * 3 + c) * 384 + (p / 24) * 16 + ky) * 384 + (p % 24) * 16 + kx];
}
__global__ void assemble_tokens_kernel(const float* __restrict__ cp, const float* __restrict__ cls_t,
                                       const float* __restrict__ pos, float* __restrict__ x) {
    long long idx = (long long)blockIdx.x * blockDim.x + threadIdx.x;
    if (idx >= (long long)B_ * S_ * D_) return;
    int j = (int)(idx % D_); long long bi = idx / D_;
    int i = (int)(bi % S_), b = (int)(bi / S_);
    float v;
    if (i == 0) v = cls_t[j];
    else {
        int flat = (i - 1) * D_ + j;
        v = cp[((size_t)b * NP + flat % NP) * D_ + flat / NP];
    }
    x[idx] = v + pos[(size_t)i * D_ + j];
}

// ====== fp32 SGEMM (head only) ======
__global__ __launch_bounds__(256) void gemm_kernel(
    const float* __restrict__ A, const float* __restrict__ Bm,
    const float* __restrict__ bias, float* __restrict__ C, int Mr, int N, int K) {
    __shared__ float As[16][132], Bs[16][128];
    int t = threadIdx.x;
    int bm = blockIdx.y * 128, bn = blockIdx.x * 128;
    int tm = (t / 16) * 8, tn = (t % 16) * 8;
    float acc[8][8] = {};
    for (int k0 = 0; k0 < K; k0 += 16) {
        #pragma unroll
        for (int i = 0; i < 2; i++) {
            int v = t + i * 256, m = v >> 2, c4 = (v & 3) * 4;
            int gm = bm + m;
            float4 val = make_float4(0,0,0,0);
            if (gm < Mr) val = *(const float4*)(A + (size_t)gm * K + k0 + c4);
            As[c4][m] = val.x; As[c4+1][m] = val.y; As[c4+2][m] = val.z; As[c4+3][m] = val.w;
        }
        #pragma unroll
        for (int i = 0; i < 2; i++) {
            int v = t + i * 256, kk = v >> 5, c4 = (v & 31) * 4;
            int gn = bn + c4;
            float4 val = make_float4(0,0,0,0);
            const float* p = Bm + (size_t)(k0 + kk) * N;
            if (gn + 3 < N) val = *(const float4*)(p + gn);
            else if (gn < N) {
                val.x = p[gn];
                if (gn + 1 < N) val.y = p[gn+1];
                if (gn + 2 < N) val.z = p[gn+2];
            }
            *(float4*)(&Bs[kk][c4]) = val;
        }
        __syncthreads();
        #pragma unroll
        for (int kk = 0; kk < 16; kk++) {
            float a[8], b[8];
            #pragma unroll
            for (int i = 0; i < 8; i++) a[i] = As[kk][tm + i];
            #pragma unroll
            for (int j = 0; j < 8; j++) b[j] = Bs[kk][tn + j];
            #pragma unroll
            for (int i = 0; i < 8; i++)
                #pragma unroll
                for (int j = 0; j < 8; j++) acc[i][j] += a[i] * b[j];
        }
        __syncthreads();
    }
    #pragma unroll
    for (int i = 0; i < 8; i++) {
        int gm = bm + tm + i;
        if (gm >= Mr) continue;
        #pragma unroll
        for (int j = 0; j < 8; j++) {
            int gn = bn + tn + j;
            if (gn >= N) continue;
            C[(size_t)gm * N + gn] = acc[i][j] + (bias ? bias[gn] : 0.f);
        }
    }
}

// ====== LayerNorm ======
__global__ __launch_bounds__(256) void ln_kernel(const float* __restrict__ in, float* __restrict__ out,
                                                 const float* __restrict__ g, const float* __restrict__ bb,
                                                 long long si, long long so) {
    long long r = blockIdx.x;
    const float* p = in + r * si;
    float* po = out + r * so;
    int t = threadIdx.x;
    float v0 = p[t], v1 = p[t + 256], v2 = p[t + 512];
    __shared__ float red[256];
    red[t] = v0 + v1 + v2; __syncthreads();
    for (int s = 128; s > 0; s >>= 1) { if (t < s) red[t] += red[t + s]; __syncthreads(); }
    float mu = red[0] * (1.f / 768.f); __syncthreads();
    float d0 = v0 - mu, d1 = v1 - mu, d2 = v2 - mu;
    red[t] = d0*d0 + d1*d1 + d2*d2; __syncthreads();
    for (int s = 128; s > 0; s >>= 1) { if (t < s) red[t] += red[t + s]; __syncthreads(); }
    float rs = rsqrtf(red[0] * (1.f / 768.f) + 1e-5f); __syncthreads();
    po[t]     = d0 * rs * g[t]     + bb[t];
    po[t+256] = d1 * rs * g[t+256] + bb[t+256];
    po[t+512] = d2 * rs * g[t+512] + bb[t+512];
}

// ====== attention ======
__global__ __launch_bounds__(256) void attn_scores_kernel(const float* __restrict__ qkv, float* __restrict__ attn) {
    int bh = blockIdx.z, b = bh / H_, h = bh % H_;
    int q0 = blockIdx.y * 64, k0 = blockIdx.x * 64;
    __shared__ float Qs[64][65], Ks[64][65];
    int t = threadIdx.x;
    #pragma unroll
    for (int i = 0; i < 16; i++) {
        int e = t + i * 256, r = e >> 6, c = e & 63;
        int gq = q0 + r, gk = k0 + r;
        Qs[r][c] = (gq < S_) ? qkv[(size_t)(b * S_ + gq) * 2304 + h * 64 + c] : 0.f;
        Ks[r][c] = (gk < S_) ? qkv[(size_t)(b * S_ + gk) * 2304 + 768 + h * 64 + c] : 0.f;
    }
    __syncthreads();
    int tm = (t / 16) * 4, tn = (t % 16) * 4;
    float acc[4][4] = {};
    #pragma unroll
    for (int e = 0; e < 64; e++) {
        float a[4], bv[4];
        #pragma unroll
        for (int i = 0; i < 4; i++) a[i] = Qs[tm + i][e];
        #pragma unroll
        for (int j = 0; j < 4; j++) bv[j] = Ks[tn + j][e];
        #pragma unroll
        for (int i = 0; i < 4; i++)
            #pragma unroll
            for (int j = 0; j < 4; j++) acc[i][j] += a[i] * bv[j];
    }
    #pragma unroll
    for (int i = 0; i < 4; i++) {
        int gq = q0 + tm + i;
        if (gq >= S_) continue;
        #pragma unroll
        for (int j = 0; j < 4; j++) {
            int gk = k0 + tn + j;
            if (gk < S_) attn[((size_t)bh * S_ + gq) * S_ + gk] = acc[i][j] * SCALE_;
        }
    }
}

__global__ __launch_bounds__(256) void softmax_kernel(const float* __restrict__ in, float* __restrict__ out, int len) {
    long long row = blockIdx.x;
    const float* p = in + row * (long long)len;
    float* po = out + row * (long long)len;
    int t = threadIdx.x;
    __shared__ float red[256];
    float mx = -1e30f;
    for (int i = t; i < len; i += 256) mx = fmaxf(mx, p[i]);
    red[t] = mx; __syncthreads();
    for (int s = 128; s > 0; s >>= 1) { if (t < s) red[t] = fmaxf(red[t], red[t + s]); __syncthreads(); }
    mx = red[0]; __syncthreads();
    float sum = 0.f;
    for (int i = t; i < len; i += 256) { float e = expf(p[i] - mx); po[i] = e; sum += e; }
    red[t] = sum; __syncthreads();
    for (int s = 128; s > 0; s >>= 1) { if (t < s) red[t] += red[t + s]; __syncthreads(); }
    float inv = 1.f / red[0]; __syncthreads();
    for (int i = t; i < len; i += 256) po[i] *= inv;
}

__global__ __launch_bounds__(256) void attn_av_kernel(const float* __restrict__ attn, const float* __restrict__ qkv,
                                                      float* __restrict__ o) {
    int bh = blockIdx.y, b = bh / H_, h = bh % H_;
    int m0 = blockIdx.x * 64;
    __shared__ float Ps[64][33], Vs[32][64];
    int t = threadIdx.x;
    int tm = (t / 16) * 4, tn = (t % 16) * 4;
    float acc[4][4] = {};
    for (int k0 = 0; k0 < S_; k0 += 32) {
        #pragma unroll
        for (int i = 0; i < 8; i++) {
            int e = t + i * 256, r = e >> 5, c = e & 31;
            int gm = m0 + r, gk = k0 + c;
            Ps[r][c] = (gm < S_ && gk < S_) ? attn[((size_t)bh * S_ + gm) * S_ + gk] : 0.f;
        }
        #pragma unroll
        for (int i = 0; i < 8; i++) {
            int e = t + i * 256, r = e >> 6, c = e & 63;
            int gk = k0 + r;
            Vs[r][c] = (gk < S_) ? qkv[(size_t)(b * S_ + gk) * 2304 + 1536 + h * 64 + c] : 0.f;
        }
        __syncthreads();
        #pragma unroll
        for (int kk = 0; kk < 32; kk++) {
            float a[4], bv[4];
            #pragma unroll
            for (int i = 0; i < 4; i++) a[i] = Ps[tm + i][kk];
            #pragma unroll
            for (int j = 0; j < 4; j++) bv[j] = Vs[kk][tn + j];
            #pragma unroll
            for (int i = 0; i < 4; i++)
                #pragma unroll
                for (int j = 0; j < 4; j++) acc[i][j] += a[i] * bv[j];
        }
        __syncthreads();
    }
    #pragma unroll
    for (int i = 0; i < 4; i++) {
        int gm = m0 + tm + i;
        if (gm >= S_) continue;
        #pragma unroll
        for (int j = 0; j < 4; j++)
            o[(size_t)(b * S_ + gm) * D_ + h * 64 + tn + j] = acc[i][j];
    }
}

// ====== host ======
static void tc_gemm(const float* A, const bf16* Bh, const bf16* Bl, const float* bias,
                    const float* res, float* C, int M, int N, int K, int act) {
    gemm_mma_kernel<<<dim3(N / 128, cdiv(M, 128)), 256, MM_SMEM>>>(A, Bh, Bl, bias, res, C, M, N, K, act);
}

extern "C" void kernel_launch(void* const* d_in, const int* in_sizes, int n_in,
                              void* d_out, int out_size) {
    const float* x      = (const float*)d_in[0];
    const float* conv_w = (const float*)d_in[1];
    const float* conv_b = (const float*)d_in[2];
    const float* cls_t  = (const float*)d_in[3];
    const float* pos    = (const float*)d_in[4];
    const float* ln1_g  = (const float*)d_in[5];
    const float* ln1_b  = (const float*)d_in[6];
    const float* wqkv   = (const float*)d_in[7];
    const float* bqkv   = (const float*)d_in[8];
    const float* wmsa   = (const float*)d_in[9];
    const float* bmsa   = (const float*)d_in[10];
    const float* ln2_g  = (const float*)d_in[11];
    const float* ln2_b  = (const float*)d_in[12];
    const float* lnm_g  = (const float*)d_in[13];
    const float* lnm_b  = (const float*)d_in[14];
    const float* w1     = (const float*)d_in[15];
    const float* b1     = (const float*)d_in[16];
    const float* w2     = (const float*)d_in[17];
    const float* b2     = (const float*)d_in[18];
    const float* lnf_g  = (const float*)d_in[19];
    const float* lnf_b  = (const float*)d_in[20];
    const float* whead  = (const float*)d_in[21];
    const float* bhead  = (const float*)d_in[22];
    float* out = (float*)d_out;

    cudaFuncSetAttribute(gemm_mma_kernel, cudaFuncAttributeMaxDynamicSharedMemorySize, MM_SMEM);

    float* buf = nullptr;
    cudaGetSymbolAddress((void**)&buf, g_buf);
    float* px = buf + O_X;   float* ph = buf + O_H;   float* ph2 = buf + O_H2;
    float* po = buf + O_O;   float* pqkv = buf + O_QKV; float* pattn = buf + O_ATTN;
    float* pm1 = buf + O_M1; float* pbpack = buf + O_BPACK;
    float* pcls = buf + O_CLS; float* plogits = buf + O_LOGITS;
    bf16* qkvh = (bf16*)(buf + O_QKVH); bf16* qkvl = (bf16*)(buf + O_QKVL);
    bf16* pwh  = (bf16*)(buf + O_PWH);  bf16* pwl  = (bf16*)(buf + O_PWL);
    bf16* msah = (bf16*)(buf + O_MSAH); bf16* msal = (bf16*)(buf + O_MSAL);
    bf16* w1h  = (bf16*)(buf + O_W1H);  bf16* w1l  = (bf16*)(buf + O_W1L);
    bf16* w2h  = (bf16*)(buf + O_W2H);  bf16* w2l  = (bf16*)(buf + O_W2L);

    // --- weight pre-split (per launch) ---
    pack_wqkv_split_kernel<<<cdiv(L_ * 2304 * 768, 256), 256>>>(wqkv, qkvh, qkvl);
    pack_bqkv_kernel<<<cdiv(L_ * H_ * 192, 256), 256>>>(bqkv, pbpack);
    split_kernel<<<cdiv(768 * 768, 256), 256>>>(conv_w, pwh, pwl, 768 * 768);
    split_transpose_kernel<<<dim3(768 / 32, 768 / 32, L_), 256>>>(wmsa, msah, msal, 768, 768);
    split_transpose_kernel<<<dim3(3072 / 32, 768 / 32, L_), 256>>>(w1, w1h, w1l, 768, 3072);
    split_transpose_kernel<<<dim3(768 / 32, 3072 / 32, L_), 256>>>(w2, w2h, w2l, 3072, 768);

    // --- patch embedding ---
    im2col_kernel<<<cdiv(B_ * NP * D_, 256), 256>>>(x, ph);
    tc_gemm(ph, pwh, pwl, conv_b, nullptr, pqkv, B_ * NP, D_, D_, 0);
    assemble_tokens_kernel<<<cdiv(B_ * S_ * D_, 256), 256>>>(pqkv, cls_t, pos, px);

    // --- encoder blocks ---
    for (int l = 0; l < L_; l++) {
        ln_kernel<<<BS_, 256>>>(px, ph, ln1_g + (size_t)l * D_, ln1_b + (size_t)l * D_, D_, D_);
        tc_gemm(ph, qkvh + (size_t)l * 2304 * 768, qkvl + (size_t)l * 2304 * 768,
                pbpack + (size_t)l * 2304, nullptr, pqkv, BS_, 2304, 768, 0);
        attn_scores_kernel<<<dim3(cdiv(S_, 64), cdiv(S_, 64), B_ * H_), 256>>>(pqkv, pattn);
        softmax_kernel<<<B_ * H_ * S_, 256>>>(pattn, pattn, S_);
        attn_av_kernel<<<dim3(cdiv(S_, 64), B_ * H_), 256>>>(pattn, pqkv, po);
        tc_gemm(po, msah + (size_t)l * 768 * 768, msal + (size_t)l * 768 * 768,
                bmsa + (size_t)l * D_, ph, px, BS_, 768, 768, 0);
        ln_kernel<<<BS_, 256>>>(px, ph2, ln2_g + (size_t)l * D_, ln2_b + (size_t)l * D_, D_, D_);
        ln_kernel<<<BS_, 256>>>(ph2, ph2, lnm_g + (size_t)l * D_, lnm_b + (size_t)l * D_, D_, D_);
        tc_gemm(ph2, w1h + (size_t)l * 3072 * 768, w1l + (size_t)l * 3072 * 768,
                b1 + (size_t)l * MFF, nullptr, pm1, BS_, 3072, 768, 1);
        tc_gemm(pm1, w2h + (size_t)l * 768 * 3072, w2l + (size_t)l * 768 * 3072,
                b2 + (size_t)l * D_, px, px, BS_, 768, 3072, 0);
    }

    // --- head ---
    ln_kernel<<<B_, 256>>>(px, pcls, lnf_g, lnf_b, (long long)S_ * D_, D_);
    gemm_kernel<<<dim3(cdiv(NC_, 128), 1), 256>>>(pcls, whead, bhead, plogits, B_, NC_, D_);
    softmax_kernel<<<B_, 256>>>(plogits, out, NC_);
}

// round 14
// speedup vs baseline: 2.0554x; 1.1145x over previous
#include <cuda_runtime.h>
#include <cuda_bf16.h>
#include <math.h>
#include <stdint.h>

constexpr int L_ = 12, H_ = 12, D_ = 768, MFF = 3072, B_ = 32, NC_ = 1000;
constexpr int NP = 576, S_ = NP + 1, BS_ = B_ * S_;
constexpr float SCALE_ = 0.125f;

constexpr size_t BSD      = (size_t)BS_ * D_;
constexpr size_t O_X      = 0;
constexpr size_t O_H      = O_X + BSD;
constexpr size_t O_H2     = O_H + BSD;
constexpr size_t O_O      = O_H2 + BSD;
constexpr size_t O_QKV    = O_O + BSD;
constexpr size_t O_ATTN   = O_QKV + BSD * 3;
constexpr size_t O_M1     = O_ATTN + (size_t)B_ * H_ * S_ * S_;
constexpr size_t SZ_QKVW  = (size_t)L_ * 2304 * 768 / 2;
constexpr size_t SZ_PW    = (size_t)768 * 768 / 2;
constexpr size_t SZ_MSAW  = (size_t)L_ * 768 * 768 / 2;
constexpr size_t SZ_W1    = (size_t)L_ * 3072 * 768 / 2;
constexpr size_t O_QKVH   = O_M1 + (size_t)BS_ * MFF;
constexpr size_t O_QKVL   = O_QKVH + SZ_QKVW;
constexpr size_t O_PWH    = O_QKVL + SZ_QKVW;
constexpr size_t O_PWL    = O_PWH + SZ_PW;
constexpr size_t O_MSAH   = O_PWL + SZ_PW;
constexpr size_t O_MSAL   = O_MSAH + SZ_MSAW;
constexpr size_t O_W1H    = O_MSAL + SZ_MSAW;
constexpr size_t O_W1L    = O_W1H + SZ_W1;
constexpr size_t O_W2H    = O_W1L + SZ_W1;
constexpr size_t O_W2L    = O_W2H + SZ_W1;
constexpr size_t O_BPACK  = O_W2L + SZ_W1;
constexpr size_t O_CLS    = O_BPACK + (size_t)L_ * 2304;
constexpr size_t O_LOGITS = O_CLS + (size_t)B_ * D_;
constexpr size_t TOTALF   = O_LOGITS + (size_t)B_ * NC_;

__device__ __align__(16) float g_buf[TOTALF];

static inline int cdiv(int a, int b) { return (a + b - 1) / b; }

typedef __nv_bfloat16 bf16;

__device__ __forceinline__ void split2(float a, float b, uint32_t& h, uint32_t& l) {
    __nv_bfloat16 ha = __float2bfloat16_rn(a), hb = __float2bfloat16_rn(b);
    __nv_bfloat162 vh = __halves2bfloat162(ha, hb);
    __nv_bfloat162 vl = __halves2bfloat162(__float2bfloat16_rn(a - __bfloat162float(ha)),
                                           __float2bfloat16_rn(b - __bfloat162float(hb)));
    h = *(uint32_t*)&vh; l = *(uint32_t*)&vl;
}

// m16n8k16 bf16 mma (sm_80+ PTX, no arch-specific features)
__device__ __forceinline__ void mma16816(float* d, const uint32_t* a, uint32_t b0, uint32_t b1) {
    asm volatile(
        "mma.sync.aligned.m16n8k16.row.col.f32.bf16.bf16.f32 "
        "{%0,%1,%2,%3}, {%4,%5,%6,%7}, {%8,%9}, {%0,%1,%2,%3};"
        : "+f"(d[0]), "+f"(d[1]), "+f"(d[2]), "+f"(d[3])
        : "r"(a[0]), "r"(a[1]), "r"(a[2]), "r"(a[3]), "r"(b0), "r"(b1));
}

constexpr int AST = 72;                      // padded smem stride (bf16 units)
constexpr int TILE_E = 128 * AST;
constexpr int MM_SMEM = 4 * TILE_E * 2;      // 73728 bytes

// ====== HMMA GEMM: C = act(A[M,K]fp32 @ B[K,N] + bias + res), B pre-split bf16 [N,K] ======
__global__ void __launch_bounds__(256, 2) gemm_mma_kernel(
    const float* __restrict__ A, const bf16* __restrict__ Bh, const bf16* __restrict__ Bl,
    const float* __restrict__ bias, const float* __restrict__ res,
    float* __restrict__ C, int Mr, int N, int K, int act) {
    extern __shared__ bf16 sm[];
    bf16* AH = sm;
    bf16* AL = sm + TILE_E;
    bf16* BH = sm + 2 * TILE_E;
    bf16* BL = sm + 3 * TILE_E;
    const int t = threadIdx.x, lane = t & 31, warp = t >> 5;
    const int bm = blockIdx.y * 128, bn = blockIdx.x * 128;
    const int wm = (warp >> 2) * 64, wn = (warp & 3) * 32;
    const int lq = lane >> 2, kp = lane & 3;
    float acc[4][4][4] = {};

    for (int c = 0; c < K / 64; c++) {
        const int kc0 = c * 64;
        #pragma unroll
        for (int j = 0; j < 4; j++) {
            int v = t + j * 256;
            int m = v >> 3, k8 = (v & 7) * 8;
            float4 f0 = make_float4(0,0,0,0), f1 = make_float4(0,0,0,0);
            int gm = bm + m;
            if (gm < Mr) {
                const float* p = A + (size_t)gm * K + kc0 + k8;
                f0 = *(const float4*)p; f1 = *(const float4*)(p + 4);
            }
            uint4 hi, lo;
            split2(f0.x, f0.y, hi.x, lo.x); split2(f0.z, f0.w, hi.y, lo.y);
            split2(f1.x, f1.y, hi.z, lo.z); split2(f1.z, f1.w, hi.w, lo.w);
            *(uint4*)&AH[m * AST + k8] = hi;
            *(uint4*)&AL[m * AST + k8] = lo;
        }
        #pragma unroll
        for (int j = 0; j < 4; j++) {
            int v = t + j * 256;
            int n = v >> 3, k8 = (v & 7) * 8;
            size_t go = (size_t)(bn + n) * K + kc0 + k8;
            *(uint4*)&BH[n * AST + k8] = *(const uint4*)(Bh + go);
            *(uint4*)&BL[n * AST + k8] = *(const uint4*)(Bl + go);
        }
        __syncthreads();
        #pragma unroll
        for (int ks = 0; ks < 4; ks++) {
            const int cA = ks * 16 + kp * 2;
            uint32_t ah[4][4], al[4][4];
            #pragma unroll
            for (int mt = 0; mt < 4; mt++) {
                int r0 = wm + mt * 16 + lq;
                ah[mt][0] = *(uint32_t*)&AH[r0 * AST + cA];
                ah[mt][1] = *(uint32_t*)&AH[(r0 + 8) * AST + cA];
                ah[mt][2] = *(uint32_t*)&AH[r0 * AST + cA + 8];
                ah[mt][3] = *(uint32_t*)&AH[(r0 + 8) * AST + cA + 8];
                al[mt][0] = *(uint32_t*)&AL[r0 * AST + cA];
                al[mt][1] = *(uint32_t*)&AL[(r0 + 8) * AST + cA];
                al[mt][2] = *(uint32_t*)&AL[r0 * AST + cA + 8];
                al[mt][3] = *(uint32_t*)&AL[(r0 + 8) * AST + cA + 8];
            }
            #pragma unroll
            for (int nt = 0; nt < 4; nt++) {
                int n0 = wn + nt * 8 + lq;
                uint32_t bh0 = *(uint32_t*)&BH[n0 * AST + cA];
                uint32_t bh1 = *(uint32_t*)&BH[n0 * AST + cA + 8];
                uint32_t bl0 = *(uint32_t*)&BL[n0 * AST + cA];
                uint32_t bl1 = *(uint32_t*)&BL[n0 * AST + cA + 8];
                #pragma unroll
                for (int mt = 0; mt < 4; mt++) {
                    mma16816(acc[mt][nt], ah[mt], bh0, bh1);
                    mma16816(acc[mt][nt], al[mt], bh0, bh1);
                    mma16816(acc[mt][nt], ah[mt], bl0, bl1);
                }
            }
        }
        __syncthreads();
    }
    #pragma unroll
    for (int mt = 0; mt < 4; mt++) {
        #pragma unroll
        for (int half = 0; half < 2; half++) {
            int gm = bm + wm + mt * 16 + lq + half * 8;
            if (gm >= Mr) continue;
            #pragma unroll
            for (int nt = 0; nt < 4; nt++) {
                int gc = bn + wn + nt * 8 + kp * 2;
                float v0 = acc[mt][nt][half * 2 + 0];
                float v1 = acc[mt][nt][half * 2 + 1];
                if (bias) { v0 += bias[gc]; v1 += bias[gc + 1]; }
                if (res) {
                    float2 rv = *(const float2*)(res + (size_t)gm * N + gc);
                    v0 += rv.x; v1 += rv.y;
                }
                if (act == 1) {
                    v0 = 0.5f * v0 * (1.f + erff(v0 * 0.70710678f));
                    v1 = 0.5f * v1 * (1.f + erff(v1 * 0.70710678f));
                }
                *(float2*)(C + (size_t)gm * N + gc) = make_float2(v0, v1);
            }
        }
    }
}

// ====== HMMA attention scores: attn[bh] = scale * Q Kt, per (b,h), K=64 single chunk ======
__global__ void __launch_bounds__(256, 2) attn_scores_mma(
    const float* __restrict__ qkv, float* __restrict__ attn) {
    extern __shared__ bf16 sm[];
    bf16* AH = sm;
    bf16* AL = sm + TILE_E;
    bf16* BH = sm + 2 * TILE_E;
    bf16* BL = sm + 3 * TILE_E;
    const int t = threadIdx.x, lane = t & 31, warp = t >> 5;
    const int bh = blockIdx.z, b = bh / H_, h = bh % H_;
    const int q0 = blockIdx.y * 128, k0 = blockIdx.x * 128;
    const int wm = (warp >> 2) * 64, wn = (warp & 3) * 32;
    const int lq = lane >> 2, kp = lane & 3;
    float acc[4][4][4] = {};

    // stage Q (A) and K (B): [128 x 64] each, strided rows in qkv
    #pragma unroll
    for (int j = 0; j < 4; j++) {
        int v = t + j * 256;
        int m = v >> 3, k8 = (v & 7) * 8;
        float4 f0 = make_float4(0,0,0,0), f1 = make_float4(0,0,0,0);
        int gq = q0 + m;
        if (gq < S_) {
            const float* p = qkv + (size_t)(b * S_ + gq) * 2304 + h * 64 + k8;
            f0 = *(const float4*)p; f1 = *(const float4*)(p + 4);
        }
        uint4 hi, lo;
        split2(f0.x, f0.y, hi.x, lo.x); split2(f0.z, f0.w, hi.y, lo.y);
        split2(f1.x, f1.y, hi.z, lo.z); split2(f1.z, f1.w, hi.w, lo.w);
        *(uint4*)&AH[m * AST + k8] = hi;
        *(uint4*)&AL[m * AST + k8] = lo;
    }
    #pragma unroll
    for (int j = 0; j < 4; j++) {
        int v = t + j * 256;
        int n = v >> 3, k8 = (v & 7) * 8;
        float4 f0 = make_float4(0,0,0,0), f1 = make_float4(0,0,0,0);
        int gk = k0 + n;
        if (gk < S_) {
            const float* p = qkv + (size_t)(b * S_ + gk) * 2304 + 768 + h * 64 + k8;
            f0 = *(const float4*)p; f1 = *(const float4*)(p + 4);
        }
        uint4 hi, lo;
        split2(f0.x, f0.y, hi.x, lo.x); split2(f0.z, f0.w, hi.y, lo.y);
        split2(f1.x, f1.y, hi.z, lo.z); split2(f1.z, f1.w, hi.w, lo.w);
        *(uint4*)&BH[n * AST + k8] = hi;
        *(uint4*)&BL[n * AST + k8] = lo;
    }
    __syncthreads();
    #pragma unroll
    for (int ks = 0; ks < 4; ks++) {
        const int cA = ks * 16 + kp * 2;
        uint32_t ah[4][4], al[4][4];
        #pragma unroll
        for (int mt = 0; mt < 4; mt++) {
            int r0 = wm + mt * 16 + lq;
            ah[mt][0] = *(uint32_t*)&AH[r0 * AST + cA];
            ah[mt][1] = *(uint32_t*)&AH[(r0 + 8) * AST + cA];
            ah[mt][2] = *(uint32_t*)&AH[r0 * AST + cA + 8];
            ah[mt][3] = *(uint32_t*)&AH[(r0 + 8) * AST + cA + 8];
            al[mt][0] = *(uint32_t*)&AL[r0 * AST + cA];
            al[mt][1] = *(uint32_t*)&AL[(r0 + 8) * AST + cA];
            al[mt][2] = *(uint32_t*)&AL[r0 * AST + cA + 8];
            al[mt][3] = *(uint32_t*)&AL[(r0 + 8) * AST + cA + 8];
        }
        #pragma unroll
        for (int nt = 0; nt < 4; nt++) {
            int n0 = wn + nt * 8 + lq;
            uint32_t bh0 = *(uint32_t*)&BH[n0 * AST + cA];
            uint32_t bh1 = *(uint32_t*)&BH[n0 * AST + cA + 8];
            uint32_t bl0 = *(uint32_t*)&BL[n0 * AST + cA];
            uint32_t bl1 = *(uint32_t*)&BL[n0 * AST + cA + 8];
            #pragma unroll
            for (int mt = 0; mt < 4; mt++) {
                mma16816(acc[mt][nt], ah[mt], bh0, bh1);
                mma16816(acc[mt][nt], al[mt], bh0, bh1);
                mma16816(acc[mt][nt], ah[mt], bl0, bl1);
            }
        }
    }
    // epilogue: scalar stores (S=577 odd row stride, no 8B alignment)
    #pragma unroll
    for (int mt = 0; mt < 4; mt++) {
        #pragma unroll
        for (int half = 0; half < 2; half++) {
            int gq = q0 + wm + mt * 16 + lq + half * 8;
            if (gq >= S_) continue;
            float* row = attn + ((size_t)bh * S_ + gq) * S_;
            #pragma unroll
            for (int nt = 0; nt < 4; nt++) {
                int gk = k0 + wn + nt * 8 + kp * 2;
                if (gk < S_)     row[gk]     = acc[mt][nt][half * 2 + 0] * SCALE_;
                if (gk + 1 < S_) row[gk + 1] = acc[mt][nt][half * 2 + 1] * SCALE_;
            }
        }
    }
}

// ====== HMMA AV: o[bh] = P V, M=S, N=64, K=S (10 guarded chunks) ======
constexpr int AV_SMEM = (2 * 128 + 2 * 64) * AST * 2;   // PH PL (128) + VH VL (64) = 55296
__global__ void __launch_bounds__(256, 2) attn_av_mma(
    const float* __restrict__ attn, const float* __restrict__ qkv, float* __restrict__ o) {
    extern __shared__ bf16 sm[];
    bf16* PH = sm;
    bf16* PL = sm + TILE_E;
    bf16* VH = sm + 2 * TILE_E;
    bf16* VL = sm + 2 * TILE_E + 64 * AST;
    const int t = threadIdx.x, lane = t & 31, warp = t >> 5;
    const int bh = blockIdx.y, b = bh / H_, h = bh % H_;
    const int m0 = blockIdx.x * 128;
    const int wm = (warp >> 1) * 32, wn = (warp & 1) * 32;   // 4x2 warp grid: 128m x 64n
    const int lq = lane >> 2, kp = lane & 3;
    float acc[2][4][4] = {};

    for (int c = 0; c < (S_ + 63) / 64; c++) {
        const int kc0 = c * 64;
        // stage P [128m x 64k] fp32 (strided, guarded, scalar loads)
        #pragma unroll
        for (int j = 0; j < 4; j++) {
            int v = t + j * 256;
            int m = v >> 3, k8 = (v & 7) * 8;
            int gm = m0 + m;
            float f[8];
            const float* row = attn + ((size_t)bh * S_ + gm) * S_;
            #pragma unroll
            for (int e = 0; e < 8; e++) {
                int gk = kc0 + k8 + e;
                f[e] = (gm < S_ && gk < S_) ? row[gk] : 0.f;
            }
            uint4 hi, lo;
            split2(f[0], f[1], hi.x, lo.x); split2(f[2], f[3], hi.y, lo.y);
            split2(f[4], f[5], hi.z, lo.z); split2(f[6], f[7], hi.w, lo.w);
            *(uint4*)&PH[m * AST + k8] = hi;
            *(uint4*)&PL[m * AST + k8] = lo;
        }
        // stage V^T [64n x 64k]: thread t -> col n = t&63, rows g*16..+15
        {
            int n = t & 63, g = t >> 6;
            #pragma unroll
            for (int kk = 0; kk < 16; kk++) {
                int gk = kc0 + g * 16 + kk;
                float v = (gk < S_) ? qkv[(size_t)(b * S_ + gk) * 2304 + 1536 + h * 64 + n] : 0.f;
                bf16 hh = __float2bfloat16_rn(v);
                VH[n * AST + g * 16 + kk] = hh;
                VL[n * AST + g * 16 + kk] = __float2bfloat16_rn(v - __bfloat162float(hh));
            }
        }
        __syncthreads();
        #pragma unroll
        for (int ks = 0; ks < 4; ks++) {
            const int cA = ks * 16 + kp * 2;
            uint32_t ph_[2][4], pl_[2][4];
            #pragma unroll
            for (int mt = 0; mt < 2; mt++) {
                int r0 = wm + mt * 16 + lq;
                ph_[mt][0] = *(uint32_t*)&PH[r0 * AST + cA];
                ph_[mt][1] = *(uint32_t*)&PH[(r0 + 8) * AST + cA];
                ph_[mt][2] = *(uint32_t*)&PH[r0 * AST + cA + 8];
                ph_[mt][3] = *(uint32_t*)&PH[(r0 + 8) * AST + cA + 8];
                pl_[mt][0] = *(uint32_t*)&PL[r0 * AST + cA];
                pl_[mt][1] = *(uint32_t*)&PL[(r0 + 8) * AST + cA];
                pl_[mt][2] = *(uint32_t*)&PL[r0 * AST + cA + 8];
                pl_[mt][3] = *(uint32_t*)&PL[(r0 + 8) * AST + cA + 8];
            }
            #pragma unroll
            for (int nt = 0; nt < 4; nt++) {
                int n0 = wn + nt * 8 + lq;
                uint32_t vh0 = *(uint32_t*)&VH[n0 * AST + cA];
                uint32_t vh1 = *(uint32_t*)&VH[n0 * AST + cA + 8];
                uint32_t vl0 = *(uint32_t*)&VL[n0 * AST + cA];
                uint32_t vl1 = *(uint32_t*)&VL[n0 * AST + cA + 8];
                #pragma unroll
                for (int mt = 0; mt < 2; mt++) {
                    mma16816(acc[mt][nt], ph_[mt], vh0, vh1);
                    mma16816(acc[mt][nt], pl_[mt], vh0, vh1);
                    mma16816(acc[mt][nt], ph_[mt], vl0, vl1);
                }
            }
        }
        __syncthreads();
    }
    #pragma unroll
    for (int mt = 0; mt < 2; mt++) {
        #pragma unroll
        for (int half = 0; half < 2; half++) {
            int gm = m0 + wm + mt * 16 + lq + half * 8;
            if (gm >= S_) continue;
            #pragma unroll
            for (int nt = 0; nt < 4; nt++) {
                int gc = wn + nt * 8 + kp * 2;
                float v0 = acc[mt][nt][half * 2 + 0];
                float v1 = acc[mt][nt][half * 2 + 1];
                *(float2*)(o + (size_t)(b * S_ + gm) * D_ + h * 64 + gc) = make_float2(v0, v1);
            }
        }
    }
}

// ====== weight pre-split kernels ======
__global__ void split_transpose_kernel(const float* __restrict__ in, bf16* __restrict__ hi,
                                       bf16* __restrict__ lo, int K, int N) {
    __shared__ float tile[32][33];
    size_t bo = (size_t)blockIdx.z * K * N;
    int k0 = blockIdx.y * 32, n0 = blockIdx.x * 32;
    int tx = threadIdx.x & 31, ty = threadIdx.x >> 5;
    for (int i = ty; i < 32; i += 8)
        tile[i][tx] = in[bo + (size_t)(k0 + i) * N + n0 + tx];
    __syncthreads();
    for (int i = ty; i < 32; i += 8) {
        float v = tile[tx][i];
        bf16 h = __float2bfloat16_rn(v);
        size_t o = bo + (size_t)(n0 + i) * K + k0 + tx;
        hi[o] = h;
        lo[o] = __float2bfloat16_rn(v - __bfloat162float(h));
    }
}
__global__ void split_kernel(const float* __restrict__ in, bf16* __restrict__ hi,
                             bf16* __restrict__ lo, long long n) {
    long long i = (long long)blockIdx.x * blockDim.x + threadIdx.x;
    if (i >= n) return;
    float v = in[i];
    bf16 h = __float2bfloat16_rn(v);
    hi[i] = h;
    lo[i] = __float2bfloat16_rn(v - __bfloat162float(h));
}
__global__ void pack_wqkv_split_kernel(const float* __restrict__ w, bf16* __restrict__ hi,
                                       bf16* __restrict__ lo) {
    long long idx = (long long)blockIdx.x * blockDim.x + threadIdx.x;
    if (idx >= (long long)L_ * 2304 * 768) return;
    int d = (int)(idx % 768);
    long long r = idx / 768;
    int n = (int)(r % 2304), l = (int)(r / 2304);
    int part = n / 768, h = (n % 768) / 64, e = n % 64;
    float v = w[(((size_t)l * H_ + h) * D_ + d) * 192 + part * 64 + e];
    bf16 hh = __float2bfloat16_rn(v);
    hi[idx] = hh;
    lo[idx] = __float2bfloat16_rn(v - __bfloat162float(hh));
}
__global__ void pack_bqkv_kernel(const float* __restrict__ b, float* __restrict__ bp) {
    int idx = blockIdx.x * blockDim.x + threadIdx.x;
    if (idx >= L_ * H_ * 192) return;
    int ef = idx % 192, r = idx / 192, h = r % H_, l = r / H_;
    bp[(size_t)l * 2304 + (ef / 64) * 768 + h * 64 + (ef % 64)] = b[idx];
}

// ====== im2col / token assembly ======
__global__ void im2col_kernel(const float* __restrict__ x, float* __restrict__ A) {
    long long idx = (long long)blockIdx.x * blockDim.x + threadIdx.x;
    if (idx >= (long long)B_ * NP * D_) return;
    int k = (int)(idx % D_); long long bp = idx / D_;
    int p = (int)(bp % NP), b = (int)(bp / NP);
    int c = k >> 8, ky = (k >> 4) & 15, kx = k & 15;
    A[idx] = x[(((size_t)b * 3 + c) * 384 + (p / 24) * 16 + ky) * 384 + (p % 24) * 16 + kx];
}
__global__ void assemble_tokens_kernel(const float* __restrict__ cp, const float* __restrict__ cls_t,
                                       const float* __restrict__ pos, float* __restrict__ x) {
    long long idx = (long long)blockIdx.x * blockDim.x + threadIdx.x;
    if (idx >= (long long)B_ * S_ * D_) return;
    int j = (int)(idx % D_); long long bi = idx / D_;
    int i = (int)(bi % S_), b = (int)(bi / S_);
    float v;
    if (i == 0) v = cls_t[j];
    else {
        int flat = (i - 1) * D_ + j;
        v = cp[((size_t)b * NP + flat % NP) * D_ + flat / NP];
    }
    x[idx] = v + pos[(size_t)i * D_ + j];
}

// ====== fp32 SGEMM (head only) ======
__global__ __launch_bounds__(256) void gemm_kernel(
    const float* __restrict__ A, const float* __restrict__ Bm,
    const float* __restrict__ bias, float* __restrict__ C, int Mr, int N, int K) {
    __shared__ float As[16][132], Bs[16][128];
    int t = threadIdx.x;
    int bm = blockIdx.y * 128, bn = blockIdx.x * 128;
    int tm = (t / 16) * 8, tn = (t % 16) * 8;
    float acc[8][8] = {};
    for (int k0 = 0; k0 < K; k0 += 16) {
        #pragma unroll
        for (int i = 0; i < 2; i++) {
            int v = t + i * 256, m = v >> 2, c4 = (v & 3) * 4;
            int gm = bm + m;
            float4 val = make_float4(0,0,0,0);
            if (gm < Mr) val = *(const float4*)(A + (size_t)gm * K + k0 + c4);
            As[c4][m] = val.x; As[c4+1][m] = val.y; As[c4+2][m] = val.z; As[c4+3][m] = val.w;
        }
        #pragma unroll
        for (int i = 0; i < 2; i++) {
            int v = t + i * 256, kk = v >> 5, c4 = (v & 31) * 4;
            int gn = bn + c4;
            float4 val = make_float4(0,0,0,0);
            const float* p = Bm + (size_t)(k0 + kk) * N;
            if (gn + 3 < N) val = *(const float4*)(p + gn);
            else if (gn < N) {
                val.x = p[gn];
                if (gn + 1 < N) val.y = p[gn+1];
                if (gn + 2 < N) val.z = p[gn+2];
            }
            *(float4*)(&Bs[kk][c4]) = val;
        }
        __syncthreads();
        #pragma unroll
        for (int kk = 0; kk < 16; kk++) {
            float a[8], b[8];
            #pragma unroll
            for (int i = 0; i < 8; i++) a[i] = As[kk][tm + i];
            #pragma unroll
            for (int j = 0; j < 8; j++) b[j] = Bs[kk][tn + j];
            #pragma unroll
            for (int i = 0; i < 8; i++)
                #pragma unroll
                for (int j = 0; j < 8; j++) acc[i][j] += a[i] * b[j];
        }
        __syncthreads();
    }
    #pragma unroll
    for (int i = 0; i < 8; i++) {
        int gm = bm + tm + i;
        if (gm >= Mr) continue;
        #pragma unroll
        for (int j = 0; j < 8; j++) {
            int gn = bn + tn + j;
            if (gn >= N) continue;
            C[(size_t)gm * N + gn] = acc[i][j] + (bias ? bias[gn] : 0.f);
        }
    }
}

// ====== LayerNorm ======
__global__ __launch_bounds__(256) void ln_kernel(const float* __restrict__ in, float* __restrict__ out,
                                                 const float* __restrict__ g, const float* __restrict__ bb,
                                                 long long si, long long so) {
    long long r = blockIdx.x;
    const float* p = in + r * si;
    float* po = out + r * so;
    int t = threadIdx.x;
    float v0 = p[t], v1 = p[t + 256], v2 = p[t + 512];
    __shared__ float red[256];
    red[t] = v0 + v1 + v2; __syncthreads();
    for (int s = 128; s > 0; s >>= 1) { if (t < s) red[t] += red[t + s]; __syncthreads(); }
    float mu = red[0] * (1.f / 768.f); __syncthreads();
    float d0 = v0 - mu, d1 = v1 - mu, d2 = v2 - mu;
    red[t] = d0*d0 + d1*d1 + d2*d2; __syncthreads();
    for (int s = 128; s > 0; s >>= 1) { if (t < s) red[t] += red[t + s]; __syncthreads(); }
    float rs = rsqrtf(red[0] * (1.f / 768.f) + 1e-5f); __syncthreads();
    po[t]     = d0 * rs * g[t]     + bb[t];
    po[t+256] = d1 * rs * g[t+256] + bb[t+256];
    po[t+512] = d2 * rs * g[t+512] + bb[t+512];
}

// ====== row softmax ======
__global__ __launch_bounds__(256) void softmax_kernel(const float* __restrict__ in, float* __restrict__ out, int len) {
    long long row = blockIdx.x;
    const float* p = in + row * (long long)len;
    float* po = out + row * (long long)len;
    int t = threadIdx.x;
    __shared__ float red[256];
    float mx = -1e30f;
    for (int i = t; i < len; i += 256) mx = fmaxf(mx, p[i]);
    red[t] = mx; __syncthreads();
    for (int s = 128; s > 0; s >>= 1) { if (t < s) red[t] = fmaxf(red[t], red[t + s]); __syncthreads(); }
    mx = red[0]; __syncthreads();
    float sum = 0.f;
    for (int i = t; i < len; i += 256) { float e = expf(p[i] - mx); po[i] = e; sum += e; }
    red[t] = sum; __syncthreads();
    for (int s = 128; s > 0; s >>= 1) { if (t < s) red[t] += red[t + s]; __syncthreads(); }
    float inv = 1.f / red[0]; __syncthreads();
    for (int i = t; i < len; i += 256) po[i] *= inv;
}

// ====== host ======
static void tc_gemm(const float* A, const bf16* Bh, const bf16* Bl, const float* bias,
                    const float* res, float* C, int M, int N, int K, int act) {
    gemm_mma_kernel<<<dim3(N / 128, cdiv(M, 128)), 256, MM_SMEM>>>(A, Bh, Bl, bias, res, C, M, N, K, act);
}

extern "C" void kernel_launch(void* const* d_in, const int* in_sizes, int n_in,
                              void* d_out, int out_size) {
    const float* x      = (const float*)d_in[0];
    const float* conv_w = (const float*)d_in[1];
    const float* conv_b = (const float*)d_in[2];
    const float* cls_t  = (const float*)d_in[3];
    const float* pos    = (const float*)d_in[4];
    const float* ln1_g  = (const float*)d_in[5];
    const float* ln1_b  = (const float*)d_in[6];
    const float* wqkv   = (const float*)d_in[7];
    const float* bqkv   = (const float*)d_in[8];
    const float* wmsa   = (const float*)d_in[9];
    const float* bmsa   = (const float*)d_in[10];
    const float* ln2_g  = (const float*)d_in[11];
    const float* ln2_b  = (const float*)d_in[12];
    const float* lnm_g  = (const float*)d_in[13];
    const float* lnm_b  = (const float*)d_in[14];
    const float* w1     = (const float*)d_in[15];
    const float* b1     = (const float*)d_in[16];
    const float* w2     = (const float*)d_in[17];
    const float* b2     = (const float*)d_in[18];
    const float* lnf_g  = (const float*)d_in[19];
    const float* lnf_b  = (const float*)d_in[20];
    const float* whead  = (const float*)d_in[21];
    const float* bhead  = (const float*)d_in[22];
    float* out = (float*)d_out;

    cudaFuncSetAttribute(gemm_mma_kernel, cudaFuncAttributeMaxDynamicSharedMemorySize, MM_SMEM);
    cudaFuncSetAttribute(attn_scores_mma, cudaFuncAttributeMaxDynamicSharedMemorySize, MM_SMEM);
    cudaFuncSetAttribute(attn_av_mma, cudaFuncAttributeMaxDynamicSharedMemorySize, AV_SMEM);

    float* buf = nullptr;
    cudaGetSymbolAddress((void**)&buf, g_buf);
    float* px = buf + O_X;   float* ph = buf + O_H;   float* ph2 = buf + O_H2;
    float* po = buf + O_O;   float* pqkv = buf + O_QKV; float* pattn = buf + O_ATTN;
    float* pm1 = buf + O_M1; float* pbpack = buf + O_BPACK;
    float* pcls = buf + O_CLS; float* plogits = buf + O_LOGITS;
    bf16* qkvh = (bf16*)(buf + O_QKVH); bf16* qkvl = (bf16*)(buf + O_QKVL);
    bf16* pwh  = (bf16*)(buf + O_PWH);  bf16* pwl  = (bf16*)(buf + O_PWL);
    bf16* msah = (bf16*)(buf + O_MSAH); bf16* msal = (bf16*)(buf + O_MSAL);
    bf16* w1h  = (bf16*)(buf + O_W1H);  bf16* w1l  = (bf16*)(buf + O_W1L);
    bf16* w2h  = (bf16*)(buf + O_W2H);  bf16* w2l  = (bf16*)(buf + O_W2L);

    // --- weight pre-split (per launch) ---
    pack_wqkv_split_kernel<<<cdiv(L_ * 2304 * 768, 256), 256>>>(wqkv, qkvh, qkvl);
    pack_bqkv_kernel<<<cdiv(L_ * H_ * 192, 256), 256>>>(bqkv, pbpack);
    split_kernel<<<cdiv(768 * 768, 256), 256>>>(conv_w, pwh, pwl, 768 * 768);
    split_transpose_kernel<<<dim3(768 / 32, 768 / 32, L_), 256>>>(wmsa, msah, msal, 768, 768);
    split_transpose_kernel<<<dim3(3072 / 32, 768 / 32, L_), 256>>>(w1, w1h, w1l, 768, 3072);
    split_transpose_kernel<<<dim3(768 / 32, 3072 / 32, L_), 256>>>(w2, w2h, w2l, 3072, 768);

    // --- patch embedding ---
    im2col_kernel<<<cdiv(B_ * NP * D_, 256), 256>>>(x, ph);
    tc_gemm(ph, pwh, pwl, conv_b, nullptr, pqkv, B_ * NP, D_, D_, 0);
    assemble_tokens_kernel<<<cdiv(B_ * S_ * D_, 256), 256>>>(pqkv, cls_t, pos, px);

    // --- encoder blocks ---
    for (int l = 0; l < L_; l++) {
        ln_kernel<<<BS_, 256>>>(px, ph, ln1_g + (size_t)l * D_, ln1_b + (size_t)l * D_, D_, D_);
        tc_gemm(ph, qkvh + (size_t)l * 2304 * 768, qkvl + (size_t)l * 2304 * 768,
                pbpack + (size_t)l * 2304, nullptr, pqkv, BS_, 2304, 768, 0);
        attn_scores_mma<<<dim3(cdiv(S_, 128), cdiv(S_, 128), B_ * H_), 256, MM_SMEM>>>(pqkv, pattn);
        softmax_kernel<<<B_ * H_ * S_, 256>>>(pattn, pattn, S_);
        attn_av_mma<<<dim3(cdiv(S_, 128), B_ * H_), 256, AV_SMEM>>>(pattn, pqkv, po);
        tc_gemm(po, msah + (size_t)l * 768 * 768, msal + (size_t)l * 768 * 768,
                bmsa + (size_t)l * D_, ph, px, BS_, 768, 768, 0);
        ln_kernel<<<BS_, 256>>>(px, ph2, ln2_g + (size_t)l * D_, ln2_b + (size_t)l * D_, D_, D_);
        ln_kernel<<<BS_, 256>>>(ph2, ph2, lnm_g + (size_t)l * D_, lnm_b + (size_t)l * D_, D_, D_);
        tc_gemm(ph2, w1h + (size_t)l * 3072 * 768, w1l + (size_t)l * 3072 * 768,
                b1 + (size_t)l * MFF, nullptr, pm1, BS_, 3072, 768, 1);
        tc_gemm(pm1, w2h + (size_t)l * 768 * 3072, w2l + (size_t)l * 768 * 3072,
                b2 + (size_t)l * D_, px, px, BS_, 768, 3072, 0);
    }

    // --- head ---
    ln_kernel<<<B_, 256>>>(px, pcls, lnf_g, lnf_b, (long long)S_ * D_, D_);
    gemm_kernel<<<dim3(cdiv(NC_, 128), 1), 256>>>(pcls, whead, bhead, plogits, B_, NC_, D_);
    softmax_kernel<<<B_, 256>>>(plogits, out, NC_);
}

// round 15
// speedup vs baseline: 2.6934x; 1.3104x over previous
#include <cuda_runtime.h>
#include <cuda_bf16.h>
#include <math.h>
#include <stdint.h>

constexpr int L_ = 12, H_ = 12, D_ = 768, MFF = 3072, B_ = 32, NC_ = 1000;
constexpr int NP = 576, S_ = NP + 1, BS_ = B_ * S_;
constexpr float SCALE_ = 0.125f;

constexpr size_t BSD      = (size_t)BS_ * D_;
constexpr size_t O_X      = 0;
constexpr size_t O_H      = O_X + BSD;
constexpr size_t O_H2     = O_H + BSD;
constexpr size_t O_O      = O_H2 + BSD;
constexpr size_t O_QKV    = O_O + BSD;
constexpr size_t O_ATTN   = O_QKV + BSD * 3;   // unused (flash attention), kept for layout stability
constexpr size_t O_M1     = O_ATTN + (size_t)B_ * H_ * S_ * S_;
constexpr size_t SZ_QKVW  = (size_t)L_ * 2304 * 768 / 2;
constexpr size_t SZ_PW    = (size_t)768 * 768 / 2;
constexpr size_t SZ_MSAW  = (size_t)L_ * 768 * 768 / 2;
constexpr size_t SZ_W1    = (size_t)L_ * 3072 * 768 / 2;
constexpr size_t O_QKVH   = O_M1 + (size_t)BS_ * MFF;
constexpr size_t O_QKVL   = O_QKVH + SZ_QKVW;
constexpr size_t O_PWH    = O_QKVL + SZ_QKVW;
constexpr size_t O_PWL    = O_PWH + SZ_PW;
constexpr size_t O_MSAH   = O_PWL + SZ_PW;
constexpr size_t O_MSAL   = O_MSAH + SZ_MSAW;
constexpr size_t O_W1H    = O_MSAL + SZ_MSAW;
constexpr size_t O_W1L    = O_W1H + SZ_W1;
constexpr size_t O_W2H    = O_W1L + SZ_W1;
constexpr size_t O_W2L    = O_W2H + SZ_W1;
constexpr size_t O_BPACK  = O_W2L + SZ_W1;
constexpr size_t O_CLS    = O_BPACK + (size_t)L_ * 2304;
constexpr size_t O_LOGITS = O_CLS + (size_t)B_ * D_;
constexpr size_t TOTALF   = O_LOGITS + (size_t)B_ * NC_;

__device__ __align__(16) float g_buf[TOTALF];

static inline int cdiv(int a, int b) { return (a + b - 1) / b; }

typedef __nv_bfloat16 bf16;

__device__ __forceinline__ void split2(float a, float b, uint32_t& h, uint32_t& l) {
    __nv_bfloat16 ha = __float2bfloat16_rn(a), hb = __float2bfloat16_rn(b);
    __nv_bfloat162 vh = __halves2bfloat162(ha, hb);
    __nv_bfloat162 vl = __halves2bfloat162(__float2bfloat16_rn(a - __bfloat162float(ha)),
                                           __float2bfloat16_rn(b - __bfloat162float(hb)));
    h = *(uint32_t*)&vh; l = *(uint32_t*)&vl;
}

// m16n8k16 bf16 mma (sm_80+ PTX, no arch-specific features)
__device__ __forceinline__ void mma16816(float* d, const uint32_t* a, uint32_t b0, uint32_t b1) {
    asm volatile(
        "mma.sync.aligned.m16n8k16.row.col.f32.bf16.bf16.f32 "
        "{%0,%1,%2,%3}, {%4,%5,%6,%7}, {%8,%9}, {%0,%1,%2,%3};"
        : "+f"(d[0]), "+f"(d[1]), "+f"(d[2]), "+f"(d[3])
        : "r"(a[0]), "r"(a[1]), "r"(a[2]), "r"(a[3]), "r"(b0), "r"(b1));
}

constexpr int AST = 72;
constexpr int TILE_E = 128 * AST;
constexpr int MM_SMEM = 4 * TILE_E * 2;      // 73728 bytes

// ====== HMMA GEMM: C = act(A[M,K]fp32 @ B[K,N] + bias + res), B pre-split bf16 [N,K] ======
__global__ void __launch_bounds__(256, 2) gemm_mma_kernel(
    const float* __restrict__ A, const bf16* __restrict__ Bh, const bf16* __restrict__ Bl,
    const float* __restrict__ bias, const float* __restrict__ res,
    float* __restrict__ C, int Mr, int N, int K, int act) {
    extern __shared__ bf16 sm[];
    bf16* AH = sm;
    bf16* AL = sm + TILE_E;
    bf16* BH = sm + 2 * TILE_E;
    bf16* BL = sm + 3 * TILE_E;
    const int t = threadIdx.x, lane = t & 31, warp = t >> 5;
    const int bm = blockIdx.y * 128, bn = blockIdx.x * 128;
    const int wm = (warp >> 2) * 64, wn = (warp & 3) * 32;
    const int lq = lane >> 2, kp = lane & 3;
    float acc[4][4][4] = {};

    for (int c = 0; c < K / 64; c++) {
        const int kc0 = c * 64;
        #pragma unroll
        for (int j = 0; j < 4; j++) {
            int v = t + j * 256;
            int m = v >> 3, k8 = (v & 7) * 8;
            float4 f0 = make_float4(0,0,0,0), f1 = make_float4(0,0,0,0);
            int gm = bm + m;
            if (gm < Mr) {
                const float* p = A + (size_t)gm * K + kc0 + k8;
                f0 = *(const float4*)p; f1 = *(const float4*)(p + 4);
            }
            uint4 hi, lo;
            split2(f0.x, f0.y, hi.x, lo.x); split2(f0.z, f0.w, hi.y, lo.y);
            split2(f1.x, f1.y, hi.z, lo.z); split2(f1.z, f1.w, hi.w, lo.w);
            *(uint4*)&AH[m * AST + k8] = hi;
            *(uint4*)&AL[m * AST + k8] = lo;
        }
        #pragma unroll
        for (int j = 0; j < 4; j++) {
            int v = t + j * 256;
            int n = v >> 3, k8 = (v & 7) * 8;
            size_t go = (size_t)(bn + n) * K + kc0 + k8;
            *(uint4*)&BH[n * AST + k8] = *(const uint4*)(Bh + go);
            *(uint4*)&BL[n * AST + k8] = *(const uint4*)(Bl + go);
        }
        __syncthreads();
        #pragma unroll
        for (int ks = 0; ks < 4; ks++) {
            const int cA = ks * 16 + kp * 2;
            uint32_t ah[4][4], al[4][4];
            #pragma unroll
            for (int mt = 0; mt < 4; mt++) {
                int r0 = wm + mt * 16 + lq;
                ah[mt][0] = *(uint32_t*)&AH[r0 * AST + cA];
                ah[mt][1] = *(uint32_t*)&AH[(r0 + 8) * AST + cA];
                ah[mt][2] = *(uint32_t*)&AH[r0 * AST + cA + 8];
                ah[mt][3] = *(uint32_t*)&AH[(r0 + 8) * AST + cA + 8];
                al[mt][0] = *(uint32_t*)&AL[r0 * AST + cA];
                al[mt][1] = *(uint32_t*)&AL[(r0 + 8) * AST + cA];
                al[mt][2] = *(uint32_t*)&AL[r0 * AST + cA + 8];
                al[mt][3] = *(uint32_t*)&AL[(r0 + 8) * AST + cA + 8];
            }
            #pragma unroll
            for (int nt = 0; nt < 4; nt++) {
                int n0 = wn + nt * 8 + lq;
                uint32_t bh0 = *(uint32_t*)&BH[n0 * AST + cA];
                uint32_t bh1 = *(uint32_t*)&BH[n0 * AST + cA + 8];
                uint32_t bl0 = *(uint32_t*)&BL[n0 * AST + cA];
                uint32_t bl1 = *(uint32_t*)&BL[n0 * AST + cA + 8];
                #pragma unroll
                for (int mt = 0; mt < 4; mt++) {
                    mma16816(acc[mt][nt], ah[mt], bh0, bh1);
                    mma16816(acc[mt][nt], al[mt], bh0, bh1);
                    mma16816(acc[mt][nt], ah[mt], bl0, bl1);
                }
            }
        }
        __syncthreads();
    }
    #pragma unroll
    for (int mt = 0; mt < 4; mt++) {
        #pragma unroll
        for (int half = 0; half < 2; half++) {
            int gm = bm + wm + mt * 16 + lq + half * 8;
            if (gm >= Mr) continue;
            #pragma unroll
            for (int nt = 0; nt < 4; nt++) {
                int gc = bn + wn + nt * 8 + kp * 2;
                float v0 = acc[mt][nt][half * 2 + 0];
                float v1 = acc[mt][nt][half * 2 + 1];
                if (bias) { v0 += bias[gc]; v1 += bias[gc + 1]; }
                if (res) {
                    float2 rv = *(const float2*)(res + (size_t)gm * N + gc);
                    v0 += rv.x; v1 += rv.y;
                }
                if (act == 1) {
                    v0 = 0.5f * v0 * (1.f + erff(v0 * 0.70710678f));
                    v1 = 0.5f * v1 * (1.f + erff(v1 * 0.70710678f));
                }
                *(float2*)(C + (size_t)gm * N + gc) = make_float2(v0, v1);
            }
        }
    }
}

// ====== flash attention: per (b,h,q-tile 128), online softmax, no attn matrix ======
// warp w owns rows [q0 + w*16, +16). smem: QH QL [128][72], KH KL [128][72], VH VL [64][136]
constexpr int FA_VST = 136;
constexpr int FA_OQH = 0, FA_OQL = 9216, FA_OKH = 18432, FA_OKL = 27648;
constexpr int FA_OVH = 36864, FA_OVL = 45568;
constexpr int FA_SMEM = 54272 * 2;   // 108544 bytes

__global__ void __launch_bounds__(256, 1) flash_attn_kernel(
    const float* __restrict__ qkv, float* __restrict__ o) {
    extern __shared__ bf16 fsm[];
    bf16* QH = fsm + FA_OQH;
    bf16* QL = fsm + FA_OQL;
    bf16* KH = fsm + FA_OKH;
    bf16* KL = fsm + FA_OKL;
    bf16* VH = fsm + FA_OVH;
    bf16* VL = fsm + FA_OVL;
    const int t = threadIdx.x, lane = t & 31, warp = t >> 5;
    const int bh = blockIdx.y, b = bh / H_, h = bh % H_;
    const int q0 = blockIdx.x * 128;
    const int lq = lane >> 2, kp = lane & 3;
    const int wrow = warp * 16;

    // stage Q [128][64] hi/lo
    #pragma unroll
    for (int j = 0; j < 4; j++) {
        int v = t + j * 256;
        int m = v >> 3, k8 = (v & 7) * 8;
        float4 f0 = make_float4(0,0,0,0), f1 = make_float4(0,0,0,0);
        int gq = q0 + m;
        if (gq < S_) {
            const float* p = qkv + (size_t)(b * S_ + gq) * 2304 + h * 64 + k8;
            f0 = *(const float4*)p; f1 = *(const float4*)(p + 4);
        }
        uint4 hi, lo;
        split2(f0.x, f0.y, hi.x, lo.x); split2(f0.z, f0.w, hi.y, lo.y);
        split2(f1.x, f1.y, hi.z, lo.z); split2(f1.z, f1.w, hi.w, lo.w);
        *(uint4*)&QH[m * AST + k8] = hi;
        *(uint4*)&QL[m * AST + k8] = lo;
    }

    float oacc[8][4] = {};
    float m0 = -1e30f, m1 = -1e30f, l0 = 0.f, l1 = 0.f;

    for (int kv0 = 0; kv0 < S_; kv0 += 128) {
        __syncthreads();   // prev-iter MMA reads done (first iter: Q staging visible)
        // stage K chunk [128][64]
        #pragma unroll
        for (int j = 0; j < 4; j++) {
            int v = t + j * 256;
            int n = v >> 3, k8 = (v & 7) * 8;
            float4 f0 = make_float4(0,0,0,0), f1 = make_float4(0,0,0,0);
            int gk = kv0 + n;
            if (gk < S_) {
                const float* p = qkv + (size_t)(b * S_ + gk) * 2304 + 768 + h * 64 + k8;
                f0 = *(const float4*)p; f1 = *(const float4*)(p + 4);
            }
            uint4 hi, lo;
            split2(f0.x, f0.y, hi.x, lo.x); split2(f0.z, f0.w, hi.y, lo.y);
            split2(f1.x, f1.y, hi.z, lo.z); split2(f1.z, f1.w, hi.w, lo.w);
            *(uint4*)&KH[n * AST + k8] = hi;
            *(uint4*)&KL[n * AST + k8] = lo;
        }
        // stage V^T [64 n][128 k]
        {
            int n = t & 63, g = t >> 6;
            #pragma unroll
            for (int kk = 0; kk < 32; kk++) {
                int kloc = g * 32 + kk;
                int gk = kv0 + kloc;
                float v = (gk < S_) ? qkv[(size_t)(b * S_ + gk) * 2304 + 1536 + h * 64 + n] : 0.f;
                bf16 hh = __float2bfloat16_rn(v);
                VH[n * FA_VST + kloc] = hh;
                VL[n * FA_VST + kloc] = __float2bfloat16_rn(v - __bfloat162float(hh));
            }
        }
        __syncthreads();

        // S = Q K^T (3-term split), 16 rows x 128 cols per warp
        float sacc[16][4];
        #pragma unroll
        for (int nt = 0; nt < 16; nt++)
            #pragma unroll
            for (int cc = 0; cc < 4; cc++) sacc[nt][cc] = 0.f;
        #pragma unroll
        for (int ks = 0; ks < 4; ks++) {
            const int cA = ks * 16 + kp * 2;
            int r0 = wrow + lq;
            uint32_t qh[4], ql_[4];
            qh[0] = *(uint32_t*)&QH[r0 * AST + cA];
            qh[1] = *(uint32_t*)&QH[(r0 + 8) * AST + cA];
            qh[2] = *(uint32_t*)&QH[r0 * AST + cA + 8];
            qh[3] = *(uint32_t*)&QH[(r0 + 8) * AST + cA + 8];
            ql_[0] = *(uint32_t*)&QL[r0 * AST + cA];
            ql_[1] = *(uint32_t*)&QL[(r0 + 8) * AST + cA];
            ql_[2] = *(uint32_t*)&QL[r0 * AST + cA + 8];
            ql_[3] = *(uint32_t*)&QL[(r0 + 8) * AST + cA + 8];
            #pragma unroll
            for (int nt = 0; nt < 16; nt++) {
                int n0 = nt * 8 + lq;
                uint32_t kh0 = *(uint32_t*)&KH[n0 * AST + cA];
                uint32_t kh1 = *(uint32_t*)&KH[n0 * AST + cA + 8];
                uint32_t kl0 = *(uint32_t*)&KL[n0 * AST + cA];
                uint32_t kl1 = *(uint32_t*)&KL[n0 * AST + cA + 8];
                mma16816(sacc[nt], qh, kh0, kh1);
                mma16816(sacc[nt], ql_, kh0, kh1);
                mma16816(sacc[nt], qh, kl0, kl1);
            }
        }
        // scale + clamp invalid cols
        bool last = (kv0 + 128 > S_);
        #pragma unroll
        for (int nt = 0; nt < 16; nt++) {
            #pragma unroll
            for (int cc = 0; cc < 4; cc++) {
                float s = sacc[nt][cc] * SCALE_;
                if (last) {
                    int col = kv0 + nt * 8 + kp * 2 + (cc & 1);
                    if (col >= S_) s = -1e30f;
                }
                sacc[nt][cc] = s;
            }
        }
        // row max
        float mx0 = -1e30f, mx1 = -1e30f;
        #pragma unroll
        for (int nt = 0; nt < 16; nt++) {
            mx0 = fmaxf(mx0, fmaxf(sacc[nt][0], sacc[nt][1]));
            mx1 = fmaxf(mx1, fmaxf(sacc[nt][2], sacc[nt][3]));
        }
        mx0 = fmaxf(mx0, __shfl_xor_sync(0xffffffffu, mx0, 1));
        mx0 = fmaxf(mx0, __shfl_xor_sync(0xffffffffu, mx0, 2));
        mx1 = fmaxf(mx1, __shfl_xor_sync(0xffffffffu, mx1, 1));
        mx1 = fmaxf(mx1, __shfl_xor_sync(0xffffffffu, mx1, 2));
        float mn0 = fmaxf(m0, mx0), mn1 = fmaxf(m1, mx1);
        float cr0 = __expf(m0 - mn0), cr1 = __expf(m1 - mn1);
        m0 = mn0; m1 = mn1;
        l0 *= cr0; l1 *= cr1;
        #pragma unroll
        for (int nt = 0; nt < 8; nt++) {
            oacc[nt][0] *= cr0; oacc[nt][1] *= cr0;
            oacc[nt][2] *= cr1; oacc[nt][3] *= cr1;
        }
        // P = exp(S - m), rowsum
        float sm0 = 0.f, sm1 = 0.f;
        #pragma unroll
        for (int nt = 0; nt < 16; nt++) {
            float p0 = __expf(sacc[nt][0] - mn0);
            float p1 = __expf(sacc[nt][1] - mn0);
            float p2 = __expf(sacc[nt][2] - mn1);
            float p3 = __expf(sacc[nt][3] - mn1);
            sacc[nt][0] = p0; sacc[nt][1] = p1; sacc[nt][2] = p2; sacc[nt][3] = p3;
            sm0 += p0 + p1; sm1 += p2 + p3;
        }
        sm0 += __shfl_xor_sync(0xffffffffu, sm0, 1);
        sm0 += __shfl_xor_sync(0xffffffffu, sm0, 2);
        sm1 += __shfl_xor_sync(0xffffffffu, sm1, 1);
        sm1 += __shfl_xor_sync(0xffffffffu, sm1, 2);
        l0 += sm0; l1 += sm1;
        // O += P V (P frags built from S registers; 2-term P split x V split = 3 MMAs)
        #pragma unroll
        for (int j = 0; j < 8; j++) {
            float* pa = sacc[2 * j];
            float* pb = sacc[2 * j + 1];
            uint32_t ph[4], pl[4];
            split2(pa[0], pa[1], ph[0], pl[0]);
            split2(pa[2], pa[3], ph[1], pl[1]);
            split2(pb[0], pb[1], ph[2], pl[2]);
            split2(pb[2], pb[3], ph[3], pl[3]);
            const int cV = j * 16 + kp * 2;
            #pragma unroll
            for (int nt = 0; nt < 8; nt++) {
                int n0 = nt * 8 + lq;
                uint32_t vh0 = *(uint32_t*)&VH[n0 * FA_VST + cV];
                uint32_t vh1 = *(uint32_t*)&VH[n0 * FA_VST + cV + 8];
                uint32_t vl0 = *(uint32_t*)&VL[n0 * FA_VST + cV];
                uint32_t vl1 = *(uint32_t*)&VL[n0 * FA_VST + cV + 8];
                mma16816(oacc[nt], ph, vh0, vh1);
                mma16816(oacc[nt], pl, vh0, vh1);
                mma16816(oacc[nt], ph, vl0, vl1);
            }
        }
    }
    // write O / l
    float inv0 = (l0 > 0.f) ? 1.f / l0 : 0.f;
    float inv1 = (l1 > 0.f) ? 1.f / l1 : 0.f;
    int gm0 = q0 + wrow + lq, gm1 = gm0 + 8;
    #pragma unroll
    for (int nt = 0; nt < 8; nt++) {
        int gc = h * 64 + nt * 8 + kp * 2;
        if (gm0 < S_)
            *(float2*)(o + (size_t)(b * S_ + gm0) * D_ + gc) =
                make_float2(oacc[nt][0] * inv0, oacc[nt][1] * inv0);
        if (gm1 < S_)
            *(float2*)(o + (size_t)(b * S_ + gm1) * D_ + gc) =
                make_float2(oacc[nt][2] * inv1, oacc[nt][3] * inv1);
    }
}

// ====== weight pre-split kernels ======
__global__ void split_transpose_kernel(const float* __restrict__ in, bf16* __restrict__ hi,
                                       bf16* __restrict__ lo, int K, int N) {
    __shared__ float tile[32][33];
    size_t bo = (size_t)blockIdx.z * K * N;
    int k0 = blockIdx.y * 32, n0 = blockIdx.x * 32;
    int tx = threadIdx.x & 31, ty = threadIdx.x >> 5;
    for (int i = ty; i < 32; i += 8)
        tile[i][tx] = in[bo + (size_t)(k0 + i) * N + n0 + tx];
    __syncthreads();
    for (int i = ty; i < 32; i += 8) {
        float v = tile[tx][i];
        bf16 h = __float2bfloat16_rn(v);
        size_t o = bo + (size_t)(n0 + i) * K + k0 + tx;
        hi[o] = h;
        lo[o] = __float2bfloat16_rn(v - __bfloat162float(h));
    }
}
__global__ void split_kernel(const float* __restrict__ in, bf16* __restrict__ hi,
                             bf16* __restrict__ lo, long long n) {
    long long i = (long long)blockIdx.x * blockDim.x + threadIdx.x;
    if (i >= n) return;
    float v = in[i];
    bf16 h = __float2bfloat16_rn(v);
    hi[i] = h;
    lo[i] = __float2bfloat16_rn(v - __bfloat162float(h));
}
__global__ void pack_wqkv_split_kernel(const float* __restrict__ w, bf16* __restrict__ hi,
                                       bf16* __restrict__ lo) {
    long long idx = (long long)blockIdx.x * blockDim.x + threadIdx.x;
    if (idx >= (long long)L_ * 2304 * 768) return;
    int d = (int)(idx % 768);
    long long r = idx / 768;
    int n = (int)(r % 2304), l = (int)(r / 2304);
    int part = n / 768, h = (n % 768) / 64, e = n % 64;
    float v = w[(((size_t)l * H_ + h) * D_ + d) * 192 + part * 64 + e];
    bf16 hh = __float2bfloat16_rn(v);
    hi[idx] = hh;
    lo[idx] = __float2bfloat16_rn(v - __bfloat162float(hh));
}
__global__ void pack_bqkv_kernel(const float* __restrict__ b, float* __restrict__ bp) {
    int idx = blockIdx.x * blockDim.x + threadIdx.x;
    if (idx >= L_ * H_ * 192) return;
    int ef = idx % 192, r = idx / 192, h = r % H_, l = r / H_;
    bp[(size_t)l * 2304 + (ef / 64) * 768 + h * 64 + (ef % 64)] = b[idx];
}

// ====== im2col / token assembly ======
__global__ void im2col_kernel(const float* __restrict__ x, float* __restrict__ A) {
    long long idx = (long long)blockIdx.x * blockDim.x + threadIdx.x;
    if (idx >= (long long)B_ * NP * D_) return;
    int k = (int)(idx % D_); long long bp = idx / D_;
    int p = (int)(bp % NP), b = (int)(bp / NP);
    int c = k >> 8, ky = (k >> 4) & 15, kx = k & 15;
    A[idx] = x[(((size_t)b * 3 + c) * 384 + (p / 24) * 16 + ky) * 384 + (p % 24) * 16 + kx];
}
__global__ void assemble_tokens_kernel(const float* __restrict__ cp, const float* __restrict__ cls_t,
                                       const float* __restrict__ pos, float* __restrict__ x) {
    long long idx = (long long)blockIdx.x * blockDim.x + threadIdx.x;
    if (idx >= (long long)B_ * S_ * D_) return;
    int j = (int)(idx % D_); long long bi = idx / D_;
    int i = (int)(bi % S_), b = (int)(bi / S_);
    float v;
    if (i == 0) v = cls_t[j];
    else {
        int flat = (i - 1) * D_ + j;
        v = cp[((size_t)b * NP + flat % NP) * D_ + flat / NP];
    }
    x[idx] = v + pos[(size_t)i * D_ + j];
}

// ====== fp32 SGEMM (head only) ======
__global__ __launch_bounds__(256) void gemm_kernel(
    const float* __restrict__ A, const float* __restrict__ Bm,
    const float* __restrict__ bias, float* __restrict__ C, int Mr, int N, int K) {
    __shared__ float As[16][132], Bs[16][128];
    int t = threadIdx.x;
    int bm = blockIdx.y * 128, bn = blockIdx.x * 128;
    int tm = (t / 16) * 8, tn = (t % 16) * 8;
    float acc[8][8] = {};
    for (int k0 = 0; k0 < K; k0 += 16) {
        #pragma unroll
        for (int i = 0; i < 2; i++) {
            int v = t + i * 256, m = v >> 2, c4 = (v & 3) * 4;
            int gm = bm + m;
            float4 val = make_float4(0,0,0,0);
            if (gm < Mr) val = *(const float4*)(A + (size_t)gm * K + k0 + c4);
            As[c4][m] = val.x; As[c4+1][m] = val.y; As[c4+2][m] = val.z; As[c4+3][m] = val.w;
        }
        #pragma unroll
        for (int i = 0; i < 2; i++) {
            int v = t + i * 256, kk = v >> 5, c4 = (v & 31) * 4;
            int gn = bn + c4;
            float4 val = make_float4(0,0,0,0);
            const float* p = Bm + (size_t)(k0 + kk) * N;
            if (gn + 3 < N) val = *(const float4*)(p + gn);
            else if (gn < N) {
                val.x = p[gn];
                if (gn + 1 < N) val.y = p[gn+1];
                if (gn + 2 < N) val.z = p[gn+2];
            }
            *(float4*)(&Bs[kk][c4]) = val;
        }
        __syncthreads();
        #pragma unroll
        for (int kk = 0; kk < 16; kk++) {
            float a[8], b[8];
            #pragma unroll
            for (int i = 0; i < 8; i++) a[i] = As[kk][tm + i];
            #pragma unroll
            for (int j = 0; j < 8; j++) b[j] = Bs[kk][tn + j];
            #pragma unroll
            for (int i = 0; i < 8; i++)
                #pragma unroll
                for (int j = 0; j < 8; j++) acc[i][j] += a[i] * b[j];
        }
        __syncthreads();
    }
    #pragma unroll
    for (int i = 0; i < 8; i++) {
        int gm = bm + tm + i;
        if (gm >= Mr) continue;
        #pragma unroll
        for (int j = 0; j < 8; j++) {
            int gn = bn + tn + j;
            if (gn >= N) continue;
            C[(size_t)gm * N + gn] = acc[i][j] + (bias ? bias[gn] : 0.f);
        }
    }
}

// ====== LayerNorm ======
__global__ __launch_bounds__(256) void ln_kernel(const float* __restrict__ in, float* __restrict__ out,
                                                 const float* __restrict__ g, const float* __restrict__ bb,
                                                 long long si, long long so) {
    long long r = blockIdx.x;
    const float* p = in + r * si;
    float* po = out + r * so;
    int t = threadIdx.x;
    float v0 = p[t], v1 = p[t + 256], v2 = p[t + 512];
    __shared__ float red[256];
    red[t] = v0 + v1 + v2; __syncthreads();
    for (int s = 128; s > 0; s >>= 1) { if (t < s) red[t] += red[t + s]; __syncthreads(); }
    float mu = red[0] * (1.f / 768.f); __syncthreads();
    float d0 = v0 - mu, d1 = v1 - mu, d2 = v2 - mu;
    red[t] = d0*d0 + d1*d1 + d2*d2; __syncthreads();
    for (int s = 128; s > 0; s >>= 1) { if (t < s) red[t] += red[t + s]; __syncthreads(); }
    float rs = rsqrtf(red[0] * (1.f / 768.f) + 1e-5f); __syncthreads();
    po[t]     = d0 * rs * g[t]     + bb[t];
    po[t+256] = d1 * rs * g[t+256] + bb[t+256];
    po[t+512] = d2 * rs * g[t+512] + bb[t+512];
}

// ====== row softmax (head) ======
__global__ __launch_bounds__(256) void softmax_kernel(const float* __restrict__ in, float* __restrict__ out, int len) {
    long long row = blockIdx.x;
    const float* p = in + row * (long long)len;
    float* po = out + row * (long long)len;
    int t = threadIdx.x;
    __shared__ float red[256];
    float mx = -1e30f;
    for (int i = t; i < len; i += 256) mx = fmaxf(mx, p[i]);
    red[t] = mx; __syncthreads();
    for (int s = 128; s > 0; s >>= 1) { if (t < s) red[t] = fmaxf(red[t], red[t + s]); __syncthreads(); }
    mx = red[0]; __syncthreads();
    float sum = 0.f;
    for (int i = t; i < len; i += 256) { float e = expf(p[i] - mx); po[i] = e; sum += e; }
    red[t] = sum; __syncthreads();
    for (int s = 128; s > 0; s >>= 1) { if (t < s) red[t] += red[t + s]; __syncthreads(); }
    float inv = 1.f / red[0]; __syncthreads();
    for (int i = t; i < len; i += 256) po[i] *= inv;
}

// ====== host ======
static void tc_gemm(const float* A, const bf16* Bh, const bf16* Bl, const float* bias,
                    const float* res, float* C, int M, int N, int K, int act) {
    gemm_mma_kernel<<<dim3(N / 128, cdiv(M, 128)), 256, MM_SMEM>>>(A, Bh, Bl, bias, res, C, M, N, K, act);
}

extern "C" void kernel_launch(void* const* d_in, const int* in_sizes, int n_in,
                              void* d_out, int out_size) {
    const float* x      = (const float*)d_in[0];
    const float* conv_w = (const float*)d_in[1];
    const float* conv_b = (const float*)d_in[2];
    const float* cls_t  = (const float*)d_in[3];
    const float* pos    = (const float*)d_in[4];
    const float* ln1_g  = (const float*)d_in[5];
    const float* ln1_b  = (const float*)d_in[6];
    const float* wqkv   = (const float*)d_in[7];
    const float* bqkv   = (const float*)d_in[8];
    const float* wmsa   = (const float*)d_in[9];
    const float* bmsa   = (const float*)d_in[10];
    const float* ln2_g  = (const float*)d_in[11];
    const float* ln2_b  = (const float*)d_in[12];
    const float* lnm_g  = (const float*)d_in[13];
    const float* lnm_b  = (const float*)d_in[14];
    const float* w1     = (const float*)d_in[15];
    const float* b1     = (const float*)d_in[16];
    const float* w2     = (const float*)d_in[17];
    const float* b2     = (const float*)d_in[18];
    const float* lnf_g  = (const float*)d_in[19];
    const float* lnf_b  = (const float*)d_in[20];
    const float* whead  = (const float*)d_in[21];
    const float* bhead  = (const float*)d_in[22];
    float* out = (float*)d_out;

    cudaFuncSetAttribute(gemm_mma_kernel, cudaFuncAttributeMaxDynamicSharedMemorySize, MM_SMEM);
    cudaFuncSetAttribute(flash_attn_kernel, cudaFuncAttributeMaxDynamicSharedMemorySize, FA_SMEM);

    float* buf = nullptr;
    cudaGetSymbolAddress((void**)&buf, g_buf);
    float* px = buf + O_X;   float* ph = buf + O_H;   float* ph2 = buf + O_H2;
    float* po = buf + O_O;   float* pqkv = buf + O_QKV;
    float* pm1 = buf + O_M1; float* pbpack = buf + O_BPACK;
    float* pcls = buf + O_CLS; float* plogits = buf + O_LOGITS;
    bf16* qkvh = (bf16*)(buf + O_QKVH); bf16* qkvl = (bf16*)(buf + O_QKVL);
    bf16* pwh  = (bf16*)(buf + O_PWH);  bf16* pwl  = (bf16*)(buf + O_PWL);
    bf16* msah = (bf16*)(buf + O_MSAH); bf16* msal = (bf16*)(buf + O_MSAL);
    bf16* w1h  = (bf16*)(buf + O_W1H);  bf16* w1l  = (bf16*)(buf + O_W1L);
    bf16* w2h  = (bf16*)(buf + O_W2H);  bf16* w2l  = (bf16*)(buf + O_W2L);

    // --- weight pre-split (per launch) ---
    pack_wqkv_split_kernel<<<cdiv(L_ * 2304 * 768, 256), 256>>>(wqkv, qkvh, qkvl);
    pack_bqkv_kernel<<<cdiv(L_ * H_ * 192, 256), 256>>>(bqkv, pbpack);
    split_kernel<<<cdiv(768 * 768, 256), 256>>>(conv_w, pwh, pwl, 768 * 768);
    split_transpose_kernel<<<dim3(768 / 32, 768 / 32, L_), 256>>>(wmsa, msah, msal, 768, 768);
    split_transpose_kernel<<<dim3(3072 / 32, 768 / 32, L_), 256>>>(w1, w1h, w1l, 768, 3072);
    split_transpose_kernel<<<dim3(768 / 32, 3072 / 32, L_), 256>>>(w2, w2h, w2l, 3072, 768);

    // --- patch embedding ---
    im2col_kernel<<<cdiv(B_ * NP * D_, 256), 256>>>(x, ph);
    tc_gemm(ph, pwh, pwl, conv_b, nullptr, pqkv, B_ * NP, D_, D_, 0);
    assemble_tokens_kernel<<<cdiv(B_ * S_ * D_, 256), 256>>>(pqkv, cls_t, pos, px);

    // --- encoder blocks ---
    for (int l = 0; l < L_; l++) {
        ln_kernel<<<BS_, 256>>>(px, ph, ln1_g + (size_t)l * D_, ln1_b + (size_t)l * D_, D_, D_);
        tc_gemm(ph, qkvh + (size_t)l * 2304 * 768, qkvl + (size_t)l * 2304 * 768,
                pbpack + (size_t)l * 2304, nullptr, pqkv, BS_, 2304, 768, 0);
        flash_attn_kernel<<<dim3(cdiv(S_, 128), B_ * H_), 256, FA_SMEM>>>(pqkv, po);
        tc_gemm(po, msah + (size_t)l * 768 * 768, msal + (size_t)l * 768 * 768,
                bmsa + (size_t)l * D_, ph, px, BS_, 768, 768, 0);
        ln_kernel<<<BS_, 256>>>(px, ph2, ln2_g + (size_t)l * D_, ln2_b + (size_t)l * D_, D_, D_);
        ln_kernel<<<BS_, 256>>>(ph2, ph2, lnm_g + (size_t)l * D_, lnm_b + (size_t)l * D_, D_, D_);
        tc_gemm(ph2, w1h + (size_t)l * 3072 * 768, w1l + (size_t)l * 3072 * 768,
                b1 + (size_t)l * MFF, nullptr, pm1, BS_, 3072, 768, 1);
        tc_gemm(pm1, w2h + (size_t)l * 768 * 3072, w2l + (size_t)l * 768 * 3072,
                b2 + (size_t)l * D_, px, px, BS_, 768, 3072, 0);
    }

    // --- head ---
    ln_kernel<<<B_, 256>>>(px, pcls, lnf_g, lnf_b, (long long)S_ * D_, D_);
    gemm_kernel<<<dim3(cdiv(NC_, 128), 1), 256>>>(pcls, whead, bhead, plogits, B_, NC_, D_);
    softmax_kernel<<<B_, 256>>>(plogits, out, NC_);
}